// round 11
// baseline (speedup 1.0000x reference)
#include <cuda_runtime.h>
#include <cuda_bf16.h>
#include <math.h>
#include <stdint.h>

// ---------------- problem dims ----------------
#define KB   16384
#define NN   8192
#define M1   32768
#define DD   128
#define DIMI 512
#define CAP  64

// ---------------- scratch ----------------
__device__ float g_h[M1 * DD];
__device__ float g_x[NN * DD];
__device__ float g_q[NN * DD];
__device__ float g_cnorm[KB];
__device__ float g_counts[KB];
__device__ int   g_idx[NN];
__device__ __nv_bfloat16 g_xs[NN * DD];           // x hi (bf16)
__device__ __nv_bfloat16 g_cs[(size_t)KB * DD];   // codebook hi (bf16)
__device__ float g_xnorm[NN];
__device__ int   g_cmax_bits;
__device__ int   g_ccount[NN];
__device__ int   g_cand[NN * CAP];
// tf32-split weights
__device__ float g_whi[DIMI * DD];                // W_in hi  [k][n]
__device__ float g_wlo[DIMI * DD];
__device__ float g_wthi[9 * DD * DD];             // conv w hi [kk][din][dout]
__device__ float g_wtlo[9 * DD * DD];
__device__ float g_ohi[DD * DIMI];                // W_out hi [k][n]
__device__ float g_olo[DD * DIMI];

// ---------------- helpers ----------------
__device__ __forceinline__ uint32_t smem_u32(const void* p) {
    uint32_t a;
    asm("{ .reg .u64 t; cvta.to.shared.u64 t, %1; cvt.u32.u64 %0, t; }" : "=r"(a) : "l"(p));
    return a;
}
__device__ __forceinline__ void cp16(uint32_t dst, const void* src) {
    asm volatile("cp.async.cg.shared.global [%0], [%1], 16;\n" :: "r"(dst), "l"(src));
}
__device__ __forceinline__ void cp16z(uint32_t dst, const void* src, int sz) {
    asm volatile("cp.async.cg.shared.global [%0], [%1], 16, %2;\n" :: "r"(dst), "l"(src), "r"(sz));
}
#define CP_COMMIT()  asm volatile("cp.async.commit_group;\n" ::: "memory")
#define CP_WAIT0()   asm volatile("cp.async.wait_group 0;\n" ::: "memory")
#define CP_WAIT1()   asm volatile("cp.async.wait_group 1;\n" ::: "memory")

__device__ __forceinline__ void ldsm4(uint32_t& r0, uint32_t& r1, uint32_t& r2, uint32_t& r3,
                                      uint32_t a) {
    asm volatile("ldmatrix.sync.aligned.m8n8.x4.shared.b16 {%0,%1,%2,%3}, [%4];"
                 : "=r"(r0), "=r"(r1), "=r"(r2), "=r"(r3) : "r"(a));
}
__device__ __forceinline__ void mma16816(float* d, const uint32_t* a, uint32_t b0, uint32_t b1) {
    asm volatile("mma.sync.aligned.m16n8k16.row.col.f32.bf16.bf16.f32 "
                 "{%0,%1,%2,%3}, {%4,%5,%6,%7}, {%8,%9}, {%0,%1,%2,%3};"
                 : "+f"(d[0]), "+f"(d[1]), "+f"(d[2]), "+f"(d[3])
                 : "r"(a[0]), "r"(a[1]), "r"(a[2]), "r"(a[3]), "r"(b0), "r"(b1));
}
__device__ __forceinline__ void mma_tf32(float* d, const uint32_t* a, uint32_t b0, uint32_t b1) {
    asm volatile("mma.sync.aligned.m16n8k8.row.col.f32.tf32.tf32.f32 "
                 "{%0,%1,%2,%3}, {%4,%5,%6,%7}, {%8,%9}, {%0,%1,%2,%3};"
                 : "+f"(d[0]), "+f"(d[1]), "+f"(d[2]), "+f"(d[3])
                 : "r"(a[0]), "r"(a[1]), "r"(a[2]), "r"(a[3]), "r"(b0), "r"(b1));
}
__device__ __forceinline__ void tf32split(float a, uint32_t& hi, uint32_t& lo) {
    asm("cvt.rna.tf32.f32 %0, %1;" : "=r"(hi) : "f"(a));
    float lof = a - __uint_as_float(hi);
    asm("cvt.rna.tf32.f32 %0, %1;" : "=r"(lo) : "f"(lof));
}

// ============================================================
// Prep: conv weight transpose + tf32 split (also resets cmax)
// ============================================================
__global__ void k_prep_c(const float* __restrict__ cw) {
    int i = blockIdx.x * 256 + threadIdx.x;
    if (i == 0) g_cmax_bits = 0;
    if (i < 9 * DD * DD) {
        int dout = i & 127;
        int din  = (i >> 7) & 127;
        int kk   = i >> 14;
        float w = cw[(dout * DD + din) * 9 + kk];
        uint32_t hi, lo;
        tf32split(w, hi, lo);
        g_wthi[kk * (DD * DD) + din * DD + dout] = __uint_as_float(hi);
        g_wtlo[kk * (DD * DD) + din * DD + dout] = __uint_as_float(lo);
    }
}
__global__ void k_prep_wo(const float* __restrict__ W, const float* __restrict__ Wout) {
    int i = blockIdx.x * 256 + threadIdx.x;
    if (i < DIMI * DD) {
        uint32_t hi, lo;
        tf32split(W[i], hi, lo);
        g_whi[i] = __uint_as_float(hi);
        g_wlo[i] = __uint_as_float(lo);
    } else if (i < 2 * DIMI * DD) {
        int j = i - DIMI * DD;
        uint32_t hi, lo;
        tf32split(Wout[j], hi, lo);
        g_ohi[j] = __uint_as_float(hi);
        g_olo[j] = __uint_as_float(lo);
    }
}

// ============================================================
// Codebook prep fused: cnorm + bf16 split + counter zero (warp/row)
// ============================================================
__global__ void k_cbprep(const float* __restrict__ cb) {
    int k    = blockIdx.x * 8 + (threadIdx.x >> 5);
    int lane = threadIdx.x & 31;
    float4 v = ((const float4*)(cb + (size_t)k * DD))[lane];
    float s = v.x * v.x + v.y * v.y + v.z * v.z + v.w * v.w;
    unsigned short s0 = __bfloat16_as_ushort(__float2bfloat16(v.x));
    unsigned short s1 = __bfloat16_as_ushort(__float2bfloat16(v.y));
    unsigned short s2 = __bfloat16_as_ushort(__float2bfloat16(v.z));
    unsigned short s3 = __bfloat16_as_ushort(__float2bfloat16(v.w));
    uint2 u;
    u.x = (uint32_t)s0 | ((uint32_t)s1 << 16);
    u.y = (uint32_t)s2 | ((uint32_t)s3 << 16);
    ((uint2*)(g_cs + (size_t)k * DD))[lane] = u;
    #pragma unroll
    for (int o = 16; o; o >>= 1) s += __shfl_xor_sync(0xffffffffu, s, o);
    if (lane == 0) {
        g_cnorm[k]  = 0.5f * s;
        g_counts[k] = 0.f;
        if (k < NN) g_ccount[k] = 0;
        atomicMax(&g_cmax_bits, __float_as_int(sqrtf(s)));
    }
}

// ============================================================
// x hi split + |x| (one warp per token)
// ============================================================
__global__ void k_splitx() {
    int gw   = blockIdx.x * 8 + (threadIdx.x >> 5);
    int lane = threadIdx.x & 31;
    const float* xp = g_x + (size_t)gw * DD;
    float ss = 0.f;
    #pragma unroll
    for (int t = 0; t < 4; t++) {
        float v = xp[lane + t * 32];
        g_xs[(size_t)gw * DD + lane + t * 32] = __float2bfloat16(v);
        ss += v * v;
    }
    #pragma unroll
    for (int o = 16; o; o >>= 1) ss += __shfl_xor_sync(0xffffffffu, ss, o);
    if (lane == 0) g_xnorm[gw] = sqrtf(ss);
}

// ============================================================
// GEMM1 via 3xTF32 — round-8 v1 (measured 89us). M tile 128.
// ============================================================
#define G1_SMEM 143360
__global__ void __launch_bounds__(256, 1) k_gemm1(const float* __restrict__ A1,
                                                  const float* __restrict__ A0) {
    extern __shared__ char smc[];
    float*   fs = (float*)smc;
    uint32_t su = smem_u32(smc);
    int tid  = threadIdx.x;
    int wid  = tid >> 5;
    int lane = tid & 31;
    int g    = lane >> 2;
    int t    = lane & 3;
    int wm   = wid & 3;
    int wn   = wid >> 2;
    int m0   = blockIdx.x * 128;

    float acc[2][8][4];
    #pragma unroll
    for (int i = 0; i < 2; i++)
        #pragma unroll
        for (int j = 0; j < 8; j++)
            #pragma unroll
            for (int c = 0; c < 4; c++) acc[i][j][c] = 0.f;

    auto issue = [&](int ch, int buf) {
        int k0 = ch * 32;
        #pragma unroll
        for (int it = 0; it < 4; it++) {
            int idx = it * 256 + tid;
            int row = idx >> 3;
            int c4  = idx & 7;
            cp16(su + buf * 18432 + row * 144 + c4 * 16,
                 A1 + (size_t)(m0 + row) * DIMI + k0 + c4 * 4);
            cp16(su + 36864 + buf * 18432 + row * 144 + c4 * 16,
                 A0 + (size_t)(m0 + row) * DIMI + k0 + c4 * 4);
        }
        #pragma unroll
        for (int it = 0; it < 4; it++) {
            int idx = it * 256 + tid;
            int row = idx >> 5;
            int c   = idx & 31;
            cp16(su + 73728 + buf * 17408 + row * 544 + c * 16,
                 g_whi + (size_t)(k0 + row) * DD + c * 4);
            cp16(su + 108544 + buf * 17408 + row * 544 + c * 16,
                 g_wlo + (size_t)(k0 + row) * DD + c * 4);
        }
        CP_COMMIT();
    };

    issue(0, 0);
    issue(1, 1);

    for (int ch = 0; ch < 16; ch++) {
        int buf = ch & 1;
        if (ch < 15) { CP_WAIT1(); } else { CP_WAIT0(); }
        __syncthreads();

        const float* A1f = fs + buf * 4608;
        const float* A0f = fs + 9216 + buf * 4608;
        const float* BHf = fs + 18432 + buf * 4352;
        const float* BLf = fs + 27136 + buf * 4352;

        #pragma unroll
        for (int kc = 0; kc < 4; kc++) {
            uint32_t ah[2][4], al[2][4];
            #pragma unroll
            for (int mt = 0; mt < 2; mt++) {
                int r0 = wm * 32 + mt * 16 + g;
                int c0 = kc * 8 + t;
                float d0 = A1f[r0 * 36 + c0]           - A0f[r0 * 36 + c0];
                float d1 = A1f[(r0 + 8) * 36 + c0]     - A0f[(r0 + 8) * 36 + c0];
                float d2 = A1f[r0 * 36 + c0 + 4]       - A0f[r0 * 36 + c0 + 4];
                float d3 = A1f[(r0 + 8) * 36 + c0 + 4] - A0f[(r0 + 8) * 36 + c0 + 4];
                tf32split(d0, ah[mt][0], al[mt][0]);
                tf32split(d1, ah[mt][1], al[mt][1]);
                tf32split(d2, ah[mt][2], al[mt][2]);
                tf32split(d3, ah[mt][3], al[mt][3]);
            }
            uint32_t bh[8][2], bl[8][2];
            #pragma unroll
            for (int nt = 0; nt < 8; nt++) {
                int n  = wn * 64 + nt * 8 + g;
                int kr = kc * 8 + t;
                bh[nt][0] = __float_as_uint(BHf[kr * 136 + n]);
                bh[nt][1] = __float_as_uint(BHf[(kr + 4) * 136 + n]);
                bl[nt][0] = __float_as_uint(BLf[kr * 136 + n]);
                bl[nt][1] = __float_as_uint(BLf[(kr + 4) * 136 + n]);
            }
            #pragma unroll
            for (int mt = 0; mt < 2; mt++)
                #pragma unroll
                for (int nt = 0; nt < 8; nt++) {
                    mma_tf32(acc[mt][nt], ah[mt], bh[nt][0], bh[nt][1]);
                    mma_tf32(acc[mt][nt], al[mt], bh[nt][0], bh[nt][1]);
                    mma_tf32(acc[mt][nt], ah[mt], bl[nt][0], bl[nt][1]);
                }
        }
        __syncthreads();
        if (ch + 2 < 16) issue(ch + 2, buf);
    }

    #pragma unroll
    for (int mt = 0; mt < 2; mt++)
        #pragma unroll
        for (int nt = 0; nt < 8; nt++) {
            int r  = m0 + wm * 32 + mt * 16 + g;
            int cc = wn * 64 + nt * 8 + 2 * t;
            *(float2*)&g_h[(size_t)r * DD + cc]       = make_float2(acc[mt][nt][0], acc[mt][nt][1]);
            *(float2*)&g_h[(size_t)(r + 8) * DD + cc] = make_float2(acc[mt][nt][2], acc[mt][nt][3]);
        }
}

// ============================================================
// Conv via 3xTF32 (round-8, passing — keep)
// ============================================================
#define CV_SMEM 174080
__global__ void __launch_bounds__(256, 1) k_conv() {
    extern __shared__ char smc[];
    float*   fs = (float*)smc;
    uint32_t su = smem_u32(smc);
    int tid  = threadIdx.x;
    int wid  = tid >> 5;
    int lane = tid & 31;
    int g    = lane >> 2;
    int t    = lane & 3;
    int wm   = wid & 1;
    int wn   = wid >> 1;
    int p0   = blockIdx.x * 64;

    float acc[2][4][4];
    #pragma unroll
    for (int i = 0; i < 2; i++)
        #pragma unroll
        for (int j = 0; j < 4; j++)
            #pragma unroll
            for (int c = 0; c < 4; c++) acc[i][j][c] = 0.f;

    auto issue = [&](int s, int buf) {
        int kk = s >> 1;
        int ch = s & 1;
        int kh = kk / 3, kw = kk % 3;
        #pragma unroll
        for (int it = 0; it < 4; it++) {
            int idx = it * 256 + tid;
            int pl  = idx >> 4;
            int cf  = idx & 15;
            int p  = p0 + pl;
            int b  = p >> 6;
            int jj = p & 63;
            int oh = jj >> 3, ow = jj & 7;
            int ih = 2 * oh - 1 + kh;
            int iw = 2 * ow - 1 + kw;
            bool valid = ((unsigned)ih < 16u) && ((unsigned)iw < 16u);
            const float* src = valid
                ? g_h + ((size_t)(b * 256 + ih * 16 + iw) * DD + ch * 64 + cf * 4)
                : g_h;
            cp16z(su + buf * 17408 + pl * 272 + cf * 16, src, valid ? 16 : 0);
        }
        #pragma unroll
        for (int it = 0; it < 8; it++) {
            int idx = it * 256 + tid;
            int row = idx >> 5;
            int c   = idx & 31;
            size_t so = (size_t)kk * (DD * DD) + (size_t)(ch * 64 + row) * DD + c * 4;
            cp16(su + 34816 + buf * 34816 + row * 544 + c * 16, g_wthi + so);
            cp16(su + 104448 + buf * 34816 + row * 544 + c * 16, g_wtlo + so);
        }
        CP_COMMIT();
    };

    issue(0, 0);
    issue(1, 1);

    for (int s = 0; s < 18; s++) {
        int buf = s & 1;
        if (s < 17) { CP_WAIT1(); } else { CP_WAIT0(); }
        __syncthreads();

        const float* Af  = fs + buf * 4352;
        const float* BHf = fs + 8704 + buf * 8704;
        const float* BLf = fs + 26112 + buf * 8704;

        #pragma unroll
        for (int kc = 0; kc < 8; kc++) {
            uint32_t ah[2][4], al[2][4];
            #pragma unroll
            for (int mt = 0; mt < 2; mt++) {
                int r0 = wm * 32 + mt * 16 + g;
                int c0 = kc * 8 + t;
                tf32split(Af[r0 * 68 + c0],           ah[mt][0], al[mt][0]);
                tf32split(Af[(r0 + 8) * 68 + c0],     ah[mt][1], al[mt][1]);
                tf32split(Af[r0 * 68 + c0 + 4],       ah[mt][2], al[mt][2]);
                tf32split(Af[(r0 + 8) * 68 + c0 + 4], ah[mt][3], al[mt][3]);
            }
            uint32_t bh[4][2], bl[4][2];
            #pragma unroll
            for (int nt = 0; nt < 4; nt++) {
                int n  = wn * 32 + nt * 8 + g;
                int kr = kc * 8 + t;
                bh[nt][0] = __float_as_uint(BHf[kr * 136 + n]);
                bh[nt][1] = __float_as_uint(BHf[(kr + 4) * 136 + n]);
                bl[nt][0] = __float_as_uint(BLf[kr * 136 + n]);
                bl[nt][1] = __float_as_uint(BLf[(kr + 4) * 136 + n]);
            }
            #pragma unroll
            for (int mt = 0; mt < 2; mt++)
                #pragma unroll
                for (int nt = 0; nt < 4; nt++) {
                    mma_tf32(acc[mt][nt], ah[mt], bh[nt][0], bh[nt][1]);
                    mma_tf32(acc[mt][nt], al[mt], bh[nt][0], bh[nt][1]);
                    mma_tf32(acc[mt][nt], ah[mt], bl[nt][0], bl[nt][1]);
                }
        }
        __syncthreads();
        if (s + 2 < 18) issue(s + 2, buf);
    }

    #pragma unroll
    for (int mt = 0; mt < 2; mt++)
        #pragma unroll
        for (int nt = 0; nt < 4; nt++) {
            int r  = p0 + wm * 32 + mt * 16 + g;
            int cc = wn * 32 + nt * 8 + 2 * t;
            *(float2*)&g_x[(size_t)r * DD + cc]       = make_float2(acc[mt][nt][0], acc[mt][nt][1]);
            *(float2*)&g_x[(size_t)(r + 8) * DD + cc] = make_float2(acc[mt][nt][2], acc[mt][nt][3]);
        }
}

// ============================================================
// VQ approximate pass — round-8 v2 + LAGGED THRESHOLD:
// collect uses thr = min(thrS_lagged[row], lm_local) + eb,
// moving the cross-warp row-min reduction behind the pipeline
// sync. 2 syncs/iter instead of 4. Same candidate-retention proof
// (threshold is min-over-subset + 2err + slack).
// ============================================================
#define LDB      272
#define A_OFF    0                       // 128 x 272 = 34816
#define B_OFF    34816                   // 2 x 34816
#define CNS_OFF  104448                  // 2 x 128 floats
#define EB2_OFF  105472                  // 128 floats
#define RMIN_OFF 105984                  // 4 x 128 floats
#define THR_OFF  108032                  // 128 floats (lagged global row min)
#define VQ_SMEM  108544
#define NIT 32

__device__ __forceinline__ void vq_loadB(uint32_t su, int buf, int kglob, int tid) {
    #pragma unroll
    for (int t = 0; t < 8; t++) {
        int j   = t * 256 + tid;
        int row = j >> 4;
        int c   = j & 15;
        cp16(su + B_OFF + buf * 34816 + row * LDB + c * 16,
             (const char*)g_cs + ((size_t)(kglob + row) * DD + c * 8) * 2);
    }
}

__global__ void __launch_bounds__(256, 2) k_vqtc() {
    extern __shared__ char smc[];
    uint32_t su = smem_u32(smc);
    int tid  = threadIdx.x;
    int wid  = tid >> 5;
    int lane = tid & 31;
    int wm   = wid & 1;
    int wn   = wid >> 1;
    int tt   = blockIdx.x >> 2;
    int sp   = blockIdx.x & 3;
    int kb0  = sp * 4096;

    float* cns  = (float*)(smc + CNS_OFF);
    float* eb2  = (float*)(smc + EB2_OFF);
    float* rmin = (float*)(smc + RMIN_OFF);
    float* thrS = (float*)(smc + THR_OFF);

    #pragma unroll
    for (int t = 0; t < 8; t++) {
        int i   = t * 256 + tid;
        int row = i >> 4;
        int c   = i & 15;
        cp16(su + A_OFF + row * LDB + c * 16,
             (const char*)g_xs + ((size_t)(tt * 128 + row) * DD + c * 8) * 2);
    }
    vq_loadB(su, 0, kb0, tid);
    CP_COMMIT();
    vq_loadB(su, 1, kb0 + 128, tid);
    CP_COMMIT();

    if (tid < 128) {
        cns[tid]       = g_cnorm[kb0 + tid];
        cns[128 + tid] = g_cnorm[kb0 + 128 + tid];
        float cmax = __int_as_float(g_cmax_bits);
        float xn = g_xnorm[tt * 128 + tid];
        eb2[tid]  = 2.f * (0.0041f * xn * cmax) + 0.1f;
        thrS[tid] = 1e30f;
    }
    CP_WAIT1();
    __syncthreads();

    uint32_t aBase = su + A_OFF + (wm * 64 + (lane & 15)) * LDB + (lane >> 4) * 16;
    uint32_t bBase = su + B_OFF + (wn * 32 + (lane & 15)) * LDB + (lane >> 4) * 16;

    for (int it = 0; it < NIT; it++) {
        int buf = it & 1;
        float acc[4][4][4];
        #pragma unroll
        for (int mt = 0; mt < 4; mt++)
            #pragma unroll
            for (int nt = 0; nt < 4; nt++)
                #pragma unroll
                for (int c = 0; c < 4; c++) acc[mt][nt][c] = 0.f;

        #pragma unroll
        for (int ks = 0; ks < 8; ks++) {
            uint32_t a[4][4];
            #pragma unroll
            for (int mt = 0; mt < 4; mt++)
                ldsm4(a[mt][0], a[mt][1], a[mt][2], a[mt][3],
                      aBase + mt * (16 * LDB) + ks * 32);
            uint32_t b0[4], b1[4];
            #pragma unroll
            for (int np = 0; np < 2; np++) {
                uint32_t r0, r1, r2, r3;
                ldsm4(r0, r1, r2, r3,
                      bBase + buf * 34816 + np * (16 * LDB) + ks * 32);
                b0[np * 2] = r0; b1[np * 2] = r2;
                b0[np * 2 + 1] = r1; b1[np * 2 + 1] = r3;
            }
            #pragma unroll
            for (int mt = 0; mt < 4; mt++)
                #pragma unroll
                for (int nt = 0; nt < 4; nt++)
                    mma16816(acc[mt][nt], a[mt], b0[nt], b1[nt]);
        }

        // per-thread row minima (8 row-slots)
        float lm[8];
        #pragma unroll
        for (int mt = 0; mt < 4; mt++) {
            #pragma unroll
            for (int h = 0; h < 2; h++) {
                float m = 1e30f;
                #pragma unroll
                for (int nt = 0; nt < 4; nt++) {
                    int colb = wn * 32 + nt * 8 + (lane & 3) * 2;
                    float s0 = cns[buf * 128 + colb]     - acc[mt][nt][h * 2];
                    float s1 = cns[buf * 128 + colb + 1] - acc[mt][nt][h * 2 + 1];
                    m = fminf(m, fminf(s0, s1));
                }
                lm[mt * 2 + h] = m;
            }
        }
        #pragma unroll
        for (int s = 0; s < 8; s++) {
            lm[s] = fminf(lm[s], __shfl_xor_sync(0xffffffffu, lm[s], 1));
            lm[s] = fminf(lm[s], __shfl_xor_sync(0xffffffffu, lm[s], 2));
        }
        if ((lane & 3) == 0) {
            #pragma unroll
            for (int mt = 0; mt < 4; mt++)
                #pragma unroll
                for (int h = 0; h < 2; h++) {
                    int row = wm * 64 + mt * 16 + (lane >> 2) + h * 8;
                    rmin[wn * 128 + row] = lm[mt * 2 + h];
                }
        }

        // candidate collection with lagged threshold (no sync needed first)
        #pragma unroll
        for (int mt = 0; mt < 4; mt++) {
            #pragma unroll
            for (int h = 0; h < 2; h++) {
                int row = wm * 64 + mt * 16 + (lane >> 2) + h * 8;
                float thrv = fminf(thrS[row], lm[mt * 2 + h]) + eb2[row];
                if (lm[mt * 2 + h] < thrv) {
                    int tok = tt * 128 + row;
                    #pragma unroll
                    for (int nt = 0; nt < 4; nt++) {
                        int colb = wn * 32 + nt * 8 + (lane & 3) * 2;
                        #pragma unroll
                        for (int cc = 0; cc < 2; cc++) {
                            float sc = cns[buf * 128 + colb + cc] - acc[mt][nt][h * 2 + cc];
                            if (sc < thrv) {
                                int pos = atomicAdd(&g_ccount[tok], 1);
                                if (pos < CAP)
                                    g_cand[tok * CAP + pos] = kb0 + it * 128 + colb + cc;
                            }
                        }
                    }
                }
            }
        }
        __syncthreads();   // B[buf]/cns[buf] reads done; rmin writes visible; thrS reads done

        // publish global row min (lagged by one iter), overlapped with load issue
        if (tid < 128) {
            float r = fminf(fminf(rmin[tid], rmin[128 + tid]),
                            fminf(rmin[256 + tid], rmin[384 + tid]));
            thrS[tid] = fminf(thrS[tid], r);
        }
        if (it + 2 < NIT) {
            vq_loadB(su, buf, kb0 + (it + 2) * 128, tid);
            CP_COMMIT();
            if (tid < 128) cns[buf * 128 + tid] = g_cnorm[kb0 + (it + 2) * 128 + tid];
        }
        if (it + 1 < NIT) {
            if (it + 2 < NIT) { CP_WAIT1(); } else { CP_WAIT0(); }
            __syncthreads();   // thrS/cns writes visible; smem loads landed
        }
    }
}

// ============================================================
// Fused exact fp32 re-rank + NSVQ post (one warp per token)
// ============================================================
__global__ void k_respost(const float* __restrict__ cb, const float* __restrict__ rv) {
    int gw   = (blockIdx.x * blockDim.x + threadIdx.x) >> 5;
    int lane = threadIdx.x & 31;
    if (gw >= NN) return;
    int cnt = g_ccount[gw];
    const float* xp = g_x + (size_t)gw * DD;
    float x4[4];
    #pragma unroll
    for (int t = 0; t < 4; t++) x4[t] = xp[lane + t * 32];

    float bestv = 1e30f;
    int   bestk = KB;

    if (cnt <= CAP) {
        for (int i = 0; i < cnt; i++) {
            int k = g_cand[gw * CAP + i];
            const float* cp = cb + (size_t)k * DD;
            float p = 0.f;
            #pragma unroll
            for (int t = 0; t < 4; t++) p = fmaf(x4[t], cp[lane + t * 32], p);
            #pragma unroll
            for (int o = 16; o; o >>= 1) p += __shfl_xor_sync(0xffffffffu, p, o);
            float sc = g_cnorm[k] - p;
            if (sc < bestv || (sc == bestv && k < bestk)) { bestv = sc; bestk = k; }
        }
    } else {
        for (int k = lane; k < KB; k += 32) {
            const float* cp = cb + (size_t)k * DD;
            float p = 0.f;
            for (int d = 0; d < DD; d++) p = fmaf(__ldg(xp + d), __ldg(cp + d), p);
            float sc = g_cnorm[k] - p;
            if (sc < bestv || (sc == bestv && k < bestk)) { bestv = sc; bestk = k; }
        }
        #pragma unroll
        for (int o = 16; o; o >>= 1) {
            float ov = __shfl_down_sync(0xffffffffu, bestv, o);
            int   ok = __shfl_down_sync(0xffffffffu, bestk, o);
            if (ov < bestv || (ov == bestv && ok < bestk)) { bestv = ov; bestk = ok; }
        }
        bestk = __shfl_sync(0xffffffffu, bestk, 0);
    }

    const float* cp = cb + (size_t)bestk * DD;
    const float* rp = rv + (size_t)gw * DD;
    float rr[4];
    float sr = 0.f, sn = 0.f;
    #pragma unroll
    for (int t = 0; t < 4; t++) {
        int d = lane + t * 32;
        float cv = cp[d], rvv = rp[d];
        rr[t] = rvv;
        float df = x4[t] - cv;
        sr += df * df;
        sn += rvv * rvv;
    }
    #pragma unroll
    for (int o = 16; o; o >>= 1) {
        sr += __shfl_xor_sync(0xffffffffu, sr, o);
        sn += __shfl_xor_sync(0xffffffffu, sn, o);
    }
    float ratio = sqrtf(sr) / sqrtf(sn) + 1e-12f;
    float* qp = g_q + (size_t)gw * DD;
    #pragma unroll
    for (int t = 0; t < 4; t++) qp[lane + t * 32] = x4[t] + ratio * rr[t];
    if (lane == 0) {
        g_idx[gw] = bestk;
        atomicAdd(&g_counts[bestk], 1.0f);
    }
}

// ============================================================
// Final scalars (unchanged)
// ============================================================
__global__ void k_final(const int* __restrict__ used, float* __restrict__ out) {
    __shared__ float red[256];
    int tid = threadIdx.x;
    float s = 0.f;
    for (int k = tid; k < KB; k += 256) {
        float p = g_counts[k] * (1.0f / 8192.0f);
        s += p * logf(p + 1e-12f);
    }
    red[tid] = s;
    __syncthreads();
    for (int o = 128; o; o >>= 1) {
        if (tid < o) red[tid] += red[tid + o];
        __syncthreads();
    }
    if (tid == 0) out[4194304] = expf(-red[0]);
    for (int k = tid; k < KB; k += 256)
        out[4194305 + k] = (float)(used[k] + (int)g_counts[k]);
    for (int n = tid; n < NN; n += 256)
        out[4194305 + KB + n] = (float)g_idx[n];
}

// ============================================================
// Decode GEMM via 3xTF32 (keep)
// ============================================================
#define DEC_SMEM 104448
__global__ void __launch_bounds__(256, 1) k_dec(const float* __restrict__ bout,
                                                float* __restrict__ out) {
    extern __shared__ char smc[];
    float*   fs = (float*)smc;
    uint32_t su = smem_u32(smc);
    int tid  = threadIdx.x;
    int wid  = tid >> 5;
    int lane = tid & 31;
    int g    = lane >> 2;
    int t    = lane & 3;
    int wm   = wid & 3;
    int wn   = wid >> 2;
    int m0   = (blockIdx.x >> 2) * 128;
    int n0   = (blockIdx.x & 3) * 128;
    int bg0  = m0 >> 6;

    float acc[2][8][4];
    #pragma unroll
    for (int i = 0; i < 2; i++)
        #pragma unroll
        for (int j = 0; j < 8; j++)
            #pragma unroll
            for (int c = 0; c < 4; c++) acc[i][j][c] = 0.f;

    auto issue = [&](int ch, int buf) {
        int k0 = ch * 32;
        #pragma unroll
        for (int it = 0; it < 4; it++) {
            int idx = it * 256 + tid;
            int d   = idx >> 5;
            int r   = idx & 31;
            int bgl = r >> 4;
            int j4  = r & 15;
            cp16(su + buf * 17408 + d * 544 + bgl * 256 + j4 * 16,
                 g_q + (size_t)(bg0 + bgl) * 8192 + (size_t)(k0 + d) * 64 + j4 * 4);
        }
        #pragma unroll
        for (int it = 0; it < 4; it++) {
            int idx = it * 256 + tid;
            int row = idx >> 5;
            int c   = idx & 31;
            cp16(su + 34816 + buf * 17408 + row * 544 + c * 16,
                 g_ohi + (size_t)(k0 + row) * DIMI + n0 + c * 4);
            cp16(su + 69632 + buf * 17408 + row * 544 + c * 16,
                 g_olo + (size_t)(k0 + row) * DIMI + n0 + c * 4);
        }
        CP_COMMIT();
    };

    issue(0, 0);
    issue(1, 1);

    for (int ch = 0; ch < 4; ch++) {
        int buf = ch & 1;
        if (ch < 3) { CP_WAIT1(); } else { CP_WAIT0(); }
        __syncthreads();

        const float* Af  = fs + buf * 4352;
        const float* BHf = fs + 8704 + buf * 4352;
        const float* BLf = fs + 17408 + buf * 4352;

        #pragma unroll
        for (int kc = 0; kc < 4; kc++) {
            uint32_t ah[2][4], al[2][4];
            #pragma unroll
            for (int mt = 0; mt < 2; mt++) {
                int r0 = wm * 32 + mt * 16 + g;
                int c0 = kc * 8 + t;
                float d0 = Af[c0 * 136 + r0];
                float d1 = Af[c0 * 136 + r0 + 8];
                float d2 = Af[(c0 + 4) * 136 + r0];
                float d3 = Af[(c0 + 4) * 136 + r0 + 8];
                tf32split(d0, ah[mt][0], al[mt][0]);
                tf32split(d1, ah[mt][1], al[mt][1]);
                tf32split(d2, ah[mt][2], al[mt][2]);
                tf32split(d3, ah[mt][3], al[mt][3]);
            }
            uint32_t bh[8][2], bl[8][2];
            #pragma unroll
            for (int nt = 0; nt < 8; nt++) {
                int n  = wn * 64 + nt * 8 + g;
                int kr = kc * 8 + t;
                bh[nt][0] = __float_as_uint(BHf[kr * 136 + n]);
                bh[nt][1] = __float_as_uint(BHf[(kr + 4) * 136 + n]);
                bl[nt][0] = __float_as_uint(BLf[kr * 136 + n]);
                bl[nt][1] = __float_as_uint(BLf[(kr + 4) * 136 + n]);
            }
            #pragma unroll
            for (int mt = 0; mt < 2; mt++)
                #pragma unroll
                for (int nt = 0; nt < 8; nt++) {
                    mma_tf32(acc[mt][nt], ah[mt], bh[nt][0], bh[nt][1]);
                    mma_tf32(acc[mt][nt], al[mt], bh[nt][0], bh[nt][1]);
                    mma_tf32(acc[mt][nt], ah[mt], bl[nt][0], bl[nt][1]);
                }
        }
        __syncthreads();
        if (ch + 2 < 4) issue(ch + 2, buf);
    }

    #pragma unroll
    for (int mt = 0; mt < 2; mt++)
        #pragma unroll
        for (int nt = 0; nt < 8; nt++) {
            int r  = m0 + wm * 32 + mt * 16 + g;
            int cc = n0 + wn * 64 + nt * 8 + 2 * t;
            float2 bb = *(const float2*)&bout[cc];
            *(float2*)&out[(size_t)r * DIMI + cc] =
                make_float2(acc[mt][nt][0] + bb.x, acc[mt][nt][1] + bb.y);
            *(float2*)&out[(size_t)(r + 8) * DIMI + cc] =
                make_float2(acc[mt][nt][2] + bb.x, acc[mt][nt][3] + bb.y);
        }
}

// ============================================================
// Launcher: round-10 fork-join stream overlap (passing).
// ============================================================
extern "C" void kernel_launch(void* const* d_in, const int* in_sizes, int n_in,
                              void* d_out, int out_size) {
    (void)in_sizes; (void)n_in; (void)out_size;
    const float* in_f   = (const float*)d_in[0];
    const float* in_l   = (const float*)d_in[1];
    const float* rv     = (const float*)d_in[2];
    const float* cb     = (const float*)d_in[3];
    const float* W_in   = (const float*)d_in[4];
    const float* conv_w = (const float*)d_in[6];
    const float* W_out  = (const float*)d_in[8];
    const float* b_out  = (const float*)d_in[9];
    const int*   used   = (const int*)d_in[10];
    float* out = (float*)d_out;

    cudaFuncSetAttribute(k_vqtc,  cudaFuncAttributeMaxDynamicSharedMemorySize, VQ_SMEM);
    cudaFuncSetAttribute(k_gemm1, cudaFuncAttributeMaxDynamicSharedMemorySize, G1_SMEM);
    cudaFuncSetAttribute(k_conv,  cudaFuncAttributeMaxDynamicSharedMemorySize, CV_SMEM);
    cudaFuncSetAttribute(k_dec,   cudaFuncAttributeMaxDynamicSharedMemorySize, DEC_SMEM);

    cudaStream_t s1;
    cudaStreamCreateWithFlags(&s1, cudaStreamNonBlocking);
    cudaEvent_t eFork, ePrep, eRes, eJoin;
    cudaEventCreateWithFlags(&eFork, cudaEventDisableTiming);
    cudaEventCreateWithFlags(&ePrep, cudaEventDisableTiming);
    cudaEventCreateWithFlags(&eRes,  cudaEventDisableTiming);
    cudaEventCreateWithFlags(&eJoin, cudaEventDisableTiming);

    // fork: codebook + conv-weight prep on side stream, overlapped with gemm1
    cudaEventRecord(eFork, 0);
    cudaStreamWaitEvent(s1, eFork, 0);
    k_prep_c <<<576, 256, 0, s1>>>(conv_w);
    k_cbprep <<<2048, 256, 0, s1>>>(cb);
    cudaEventRecord(ePrep, s1);

    // main chain
    k_prep_wo<<<512, 256>>>(W_in, W_out);
    k_gemm1  <<<256, 256, G1_SMEM>>>(in_l, in_f);
    cudaStreamWaitEvent(0, ePrep, 0);       // conv needs g_wthi/g_wtlo
    k_conv   <<<128, 256, CV_SMEM>>>();
    k_splitx <<<1024, 256>>>();
    k_vqtc   <<<256, 256, VQ_SMEM>>>();
    k_respost<<<1024, 256>>>(cb, rv);

    // fork: final (scalars/tail of out) overlapped with decode GEMM
    cudaEventRecord(eRes, 0);
    cudaStreamWaitEvent(s1, eRes, 0);
    k_final  <<<1, 256, 0, s1>>>(used, out);
    k_dec    <<<256, 256, DEC_SMEM>>>(b_out, out);

    // join side stream back before returning (capture requirement)
    cudaEventRecord(eJoin, s1);
    cudaStreamWaitEvent(0, eJoin, 0);
}

// round 12
// speedup vs baseline: 8.5776x; 8.5776x over previous
#include <cuda_runtime.h>
#include <cuda_bf16.h>
#include <math.h>
#include <stdint.h>

// ---------------- problem dims ----------------
#define KB   16384
#define NN   8192
#define M1   32768
#define DD   128
#define DIMI 512
#define CAP  128

// ---------------- scratch ----------------
__device__ float g_h[M1 * DD];
__device__ float g_x[NN * DD];
__device__ float g_q[NN * DD];
__device__ float g_cnorm[KB];
__device__ float g_counts[KB];
__device__ int   g_idx[NN];
__device__ __nv_bfloat16 g_xs[NN * DD];           // x hi (bf16)
__device__ __nv_bfloat16 g_cs[(size_t)KB * DD];   // codebook hi (bf16)
__device__ float g_xnorm[NN];
__device__ int   g_cmax_bits;
__device__ int   g_ccount[NN];
__device__ int   g_cand[NN * CAP];
// tf32-split weights
__device__ float g_whi[DIMI * DD];                // W_in hi  [k][n]
__device__ float g_wlo[DIMI * DD];
__device__ float g_wthi[9 * DD * DD];             // conv w hi [kk][din][dout]
__device__ float g_wtlo[9 * DD * DD];
__device__ float g_ohi[DD * DIMI];                // W_out hi [k][n]
__device__ float g_olo[DD * DIMI];

// ---------------- helpers ----------------
__device__ __forceinline__ uint32_t smem_u32(const void* p) {
    uint32_t a;
    asm("{ .reg .u64 t; cvta.to.shared.u64 t, %1; cvt.u32.u64 %0, t; }" : "=r"(a) : "l"(p));
    return a;
}
__device__ __forceinline__ void cp16(uint32_t dst, const void* src) {
    asm volatile("cp.async.cg.shared.global [%0], [%1], 16;\n" :: "r"(dst), "l"(src));
}
__device__ __forceinline__ void cp16z(uint32_t dst, const void* src, int sz) {
    asm volatile("cp.async.cg.shared.global [%0], [%1], 16, %2;\n" :: "r"(dst), "l"(src), "r"(sz));
}
#define CP_COMMIT()  asm volatile("cp.async.commit_group;\n" ::: "memory")
#define CP_WAIT0()   asm volatile("cp.async.wait_group 0;\n" ::: "memory")
#define CP_WAIT1()   asm volatile("cp.async.wait_group 1;\n" ::: "memory")

__device__ __forceinline__ void ldsm4(uint32_t& r0, uint32_t& r1, uint32_t& r2, uint32_t& r3,
                                      uint32_t a) {
    asm volatile("ldmatrix.sync.aligned.m8n8.x4.shared.b16 {%0,%1,%2,%3}, [%4];"
                 : "=r"(r0), "=r"(r1), "=r"(r2), "=r"(r3) : "r"(a));
}
__device__ __forceinline__ void mma16816(float* d, const uint32_t* a, uint32_t b0, uint32_t b1) {
    asm volatile("mma.sync.aligned.m16n8k16.row.col.f32.bf16.bf16.f32 "
                 "{%0,%1,%2,%3}, {%4,%5,%6,%7}, {%8,%9}, {%0,%1,%2,%3};"
                 : "+f"(d[0]), "+f"(d[1]), "+f"(d[2]), "+f"(d[3])
                 : "r"(a[0]), "r"(a[1]), "r"(a[2]), "r"(a[3]), "r"(b0), "r"(b1));
}
__device__ __forceinline__ void mma_tf32(float* d, const uint32_t* a, uint32_t b0, uint32_t b1) {
    asm volatile("mma.sync.aligned.m16n8k8.row.col.f32.tf32.tf32.f32 "
                 "{%0,%1,%2,%3}, {%4,%5,%6,%7}, {%8,%9}, {%0,%1,%2,%3};"
                 : "+f"(d[0]), "+f"(d[1]), "+f"(d[2]), "+f"(d[3])
                 : "r"(a[0]), "r"(a[1]), "r"(a[2]), "r"(a[3]), "r"(b0), "r"(b1));
}
__device__ __forceinline__ void tf32split(float a, uint32_t& hi, uint32_t& lo) {
    asm("cvt.rna.tf32.f32 %0, %1;" : "=r"(hi) : "f"(a));
    float lof = a - __uint_as_float(hi);
    asm("cvt.rna.tf32.f32 %0, %1;" : "=r"(lo) : "f"(lof));
}

// ============================================================
// Prep: conv weight transpose + tf32 split (also resets cmax)
// ============================================================
__global__ void k_prep_c(const float* __restrict__ cw) {
    int i = blockIdx.x * 256 + threadIdx.x;
    if (i == 0) g_cmax_bits = 0;
    if (i < 9 * DD * DD) {
        int dout = i & 127;
        int din  = (i >> 7) & 127;
        int kk   = i >> 14;
        float w = cw[(dout * DD + din) * 9 + kk];
        uint32_t hi, lo;
        tf32split(w, hi, lo);
        g_wthi[kk * (DD * DD) + din * DD + dout] = __uint_as_float(hi);
        g_wtlo[kk * (DD * DD) + din * DD + dout] = __uint_as_float(lo);
    }
}
__global__ void k_prep_wo(const float* __restrict__ W, const float* __restrict__ Wout) {
    int i = blockIdx.x * 256 + threadIdx.x;
    if (i < DIMI * DD) {
        uint32_t hi, lo;
        tf32split(W[i], hi, lo);
        g_whi[i] = __uint_as_float(hi);
        g_wlo[i] = __uint_as_float(lo);
    } else if (i < 2 * DIMI * DD) {
        int j = i - DIMI * DD;
        uint32_t hi, lo;
        tf32split(Wout[j], hi, lo);
        g_ohi[j] = __uint_as_float(hi);
        g_olo[j] = __uint_as_float(lo);
    }
}

// ============================================================
// Codebook prep fused: cnorm + bf16 split + counter zero (warp/row)
// ============================================================
__global__ void k_cbprep(const float* __restrict__ cb) {
    int k    = blockIdx.x * 8 + (threadIdx.x >> 5);
    int lane = threadIdx.x & 31;
    float4 v = ((const float4*)(cb + (size_t)k * DD))[lane];
    float s = v.x * v.x + v.y * v.y + v.z * v.z + v.w * v.w;
    unsigned short s0 = __bfloat16_as_ushort(__float2bfloat16(v.x));
    unsigned short s1 = __bfloat16_as_ushort(__float2bfloat16(v.y));
    unsigned short s2 = __bfloat16_as_ushort(__float2bfloat16(v.z));
    unsigned short s3 = __bfloat16_as_ushort(__float2bfloat16(v.w));
    uint2 u;
    u.x = (uint32_t)s0 | ((uint32_t)s1 << 16);
    u.y = (uint32_t)s2 | ((uint32_t)s3 << 16);
    ((uint2*)(g_cs + (size_t)k * DD))[lane] = u;
    #pragma unroll
    for (int o = 16; o; o >>= 1) s += __shfl_xor_sync(0xffffffffu, s, o);
    if (lane == 0) {
        g_cnorm[k]  = 0.5f * s;
        g_counts[k] = 0.f;
        if (k < NN) g_ccount[k] = 0;
        atomicMax(&g_cmax_bits, __float_as_int(sqrtf(s)));
    }
}

// ============================================================
// x hi split + |x| (one warp per token)
// ============================================================
__global__ void k_splitx() {
    int gw   = blockIdx.x * 8 + (threadIdx.x >> 5);
    int lane = threadIdx.x & 31;
    const float* xp = g_x + (size_t)gw * DD;
    float ss = 0.f;
    #pragma unroll
    for (int t = 0; t < 4; t++) {
        float v = xp[lane + t * 32];
        g_xs[(size_t)gw * DD + lane + t * 32] = __float2bfloat16(v);
        ss += v * v;
    }
    #pragma unroll
    for (int o = 16; o; o >>= 1) ss += __shfl_xor_sync(0xffffffffu, ss, o);
    if (lane == 0) g_xnorm[gw] = sqrtf(ss);
}

// ============================================================
// GEMM1 via 3xTF32 — round-8 v1 (measured 89us). M tile 128.
// ============================================================
#define G1_SMEM 143360
__global__ void __launch_bounds__(256, 1) k_gemm1(const float* __restrict__ A1,
                                                  const float* __restrict__ A0) {
    extern __shared__ char smc[];
    float*   fs = (float*)smc;
    uint32_t su = smem_u32(smc);
    int tid  = threadIdx.x;
    int wid  = tid >> 5;
    int lane = tid & 31;
    int g    = lane >> 2;
    int t    = lane & 3;
    int wm   = wid & 3;
    int wn   = wid >> 2;
    int m0   = blockIdx.x * 128;

    float acc[2][8][4];
    #pragma unroll
    for (int i = 0; i < 2; i++)
        #pragma unroll
        for (int j = 0; j < 8; j++)
            #pragma unroll
            for (int c = 0; c < 4; c++) acc[i][j][c] = 0.f;

    auto issue = [&](int ch, int buf) {
        int k0 = ch * 32;
        #pragma unroll
        for (int it = 0; it < 4; it++) {
            int idx = it * 256 + tid;
            int row = idx >> 3;
            int c4  = idx & 7;
            cp16(su + buf * 18432 + row * 144 + c4 * 16,
                 A1 + (size_t)(m0 + row) * DIMI + k0 + c4 * 4);
            cp16(su + 36864 + buf * 18432 + row * 144 + c4 * 16,
                 A0 + (size_t)(m0 + row) * DIMI + k0 + c4 * 4);
        }
        #pragma unroll
        for (int it = 0; it < 4; it++) {
            int idx = it * 256 + tid;
            int row = idx >> 5;
            int c   = idx & 31;
            cp16(su + 73728 + buf * 17408 + row * 544 + c * 16,
                 g_whi + (size_t)(k0 + row) * DD + c * 4);
            cp16(su + 108544 + buf * 17408 + row * 544 + c * 16,
                 g_wlo + (size_t)(k0 + row) * DD + c * 4);
        }
        CP_COMMIT();
    };

    issue(0, 0);
    issue(1, 1);

    for (int ch = 0; ch < 16; ch++) {
        int buf = ch & 1;
        if (ch < 15) { CP_WAIT1(); } else { CP_WAIT0(); }
        __syncthreads();

        const float* A1f = fs + buf * 4608;
        const float* A0f = fs + 9216 + buf * 4608;
        const float* BHf = fs + 18432 + buf * 4352;
        const float* BLf = fs + 27136 + buf * 4352;

        #pragma unroll
        for (int kc = 0; kc < 4; kc++) {
            uint32_t ah[2][4], al[2][4];
            #pragma unroll
            for (int mt = 0; mt < 2; mt++) {
                int r0 = wm * 32 + mt * 16 + g;
                int c0 = kc * 8 + t;
                float d0 = A1f[r0 * 36 + c0]           - A0f[r0 * 36 + c0];
                float d1 = A1f[(r0 + 8) * 36 + c0]     - A0f[(r0 + 8) * 36 + c0];
                float d2 = A1f[r0 * 36 + c0 + 4]       - A0f[r0 * 36 + c0 + 4];
                float d3 = A1f[(r0 + 8) * 36 + c0 + 4] - A0f[(r0 + 8) * 36 + c0 + 4];
                tf32split(d0, ah[mt][0], al[mt][0]);
                tf32split(d1, ah[mt][1], al[mt][1]);
                tf32split(d2, ah[mt][2], al[mt][2]);
                tf32split(d3, ah[mt][3], al[mt][3]);
            }
            uint32_t bh[8][2], bl[8][2];
            #pragma unroll
            for (int nt = 0; nt < 8; nt++) {
                int n  = wn * 64 + nt * 8 + g;
                int kr = kc * 8 + t;
                bh[nt][0] = __float_as_uint(BHf[kr * 136 + n]);
                bh[nt][1] = __float_as_uint(BHf[(kr + 4) * 136 + n]);
                bl[nt][0] = __float_as_uint(BLf[kr * 136 + n]);
                bl[nt][1] = __float_as_uint(BLf[(kr + 4) * 136 + n]);
            }
            #pragma unroll
            for (int mt = 0; mt < 2; mt++)
                #pragma unroll
                for (int nt = 0; nt < 8; nt++) {
                    mma_tf32(acc[mt][nt], ah[mt], bh[nt][0], bh[nt][1]);
                    mma_tf32(acc[mt][nt], al[mt], bh[nt][0], bh[nt][1]);
                    mma_tf32(acc[mt][nt], ah[mt], bl[nt][0], bl[nt][1]);
                }
        }
        __syncthreads();
        if (ch + 2 < 16) issue(ch + 2, buf);
    }

    #pragma unroll
    for (int mt = 0; mt < 2; mt++)
        #pragma unroll
        for (int nt = 0; nt < 8; nt++) {
            int r  = m0 + wm * 32 + mt * 16 + g;
            int cc = wn * 64 + nt * 8 + 2 * t;
            *(float2*)&g_h[(size_t)r * DD + cc]       = make_float2(acc[mt][nt][0], acc[mt][nt][1]);
            *(float2*)&g_h[(size_t)(r + 8) * DD + cc] = make_float2(acc[mt][nt][2], acc[mt][nt][3]);
        }
}

// ============================================================
// Conv via 3xTF32 (round-8, passing — keep)
// ============================================================
#define CV_SMEM 174080
__global__ void __launch_bounds__(256, 1) k_conv() {
    extern __shared__ char smc[];
    float*   fs = (float*)smc;
    uint32_t su = smem_u32(smc);
    int tid  = threadIdx.x;
    int wid  = tid >> 5;
    int lane = tid & 31;
    int g    = lane >> 2;
    int t    = lane & 3;
    int wm   = wid & 1;
    int wn   = wid >> 1;
    int p0   = blockIdx.x * 64;

    float acc[2][4][4];
    #pragma unroll
    for (int i = 0; i < 2; i++)
        #pragma unroll
        for (int j = 0; j < 4; j++)
            #pragma unroll
            for (int c = 0; c < 4; c++) acc[i][j][c] = 0.f;

    auto issue = [&](int s, int buf) {
        int kk = s >> 1;
        int ch = s & 1;
        int kh = kk / 3, kw = kk % 3;
        #pragma unroll
        for (int it = 0; it < 4; it++) {
            int idx = it * 256 + tid;
            int pl  = idx >> 4;
            int cf  = idx & 15;
            int p  = p0 + pl;
            int b  = p >> 6;
            int jj = p & 63;
            int oh = jj >> 3, ow = jj & 7;
            int ih = 2 * oh - 1 + kh;
            int iw = 2 * ow - 1 + kw;
            bool valid = ((unsigned)ih < 16u) && ((unsigned)iw < 16u);
            const float* src = valid
                ? g_h + ((size_t)(b * 256 + ih * 16 + iw) * DD + ch * 64 + cf * 4)
                : g_h;
            cp16z(su + buf * 17408 + pl * 272 + cf * 16, src, valid ? 16 : 0);
        }
        #pragma unroll
        for (int it = 0; it < 8; it++) {
            int idx = it * 256 + tid;
            int row = idx >> 5;
            int c   = idx & 31;
            size_t so = (size_t)kk * (DD * DD) + (size_t)(ch * 64 + row) * DD + c * 4;
            cp16(su + 34816 + buf * 34816 + row * 544 + c * 16, g_wthi + so);
            cp16(su + 104448 + buf * 34816 + row * 544 + c * 16, g_wtlo + so);
        }
        CP_COMMIT();
    };

    issue(0, 0);
    issue(1, 1);

    for (int s = 0; s < 18; s++) {
        int buf = s & 1;
        if (s < 17) { CP_WAIT1(); } else { CP_WAIT0(); }
        __syncthreads();

        const float* Af  = fs + buf * 4352;
        const float* BHf = fs + 8704 + buf * 8704;
        const float* BLf = fs + 26112 + buf * 8704;

        #pragma unroll
        for (int kc = 0; kc < 8; kc++) {
            uint32_t ah[2][4], al[2][4];
            #pragma unroll
            for (int mt = 0; mt < 2; mt++) {
                int r0 = wm * 32 + mt * 16 + g;
                int c0 = kc * 8 + t;
                tf32split(Af[r0 * 68 + c0],           ah[mt][0], al[mt][0]);
                tf32split(Af[(r0 + 8) * 68 + c0],     ah[mt][1], al[mt][1]);
                tf32split(Af[r0 * 68 + c0 + 4],       ah[mt][2], al[mt][2]);
                tf32split(Af[(r0 + 8) * 68 + c0 + 4], ah[mt][3], al[mt][3]);
            }
            uint32_t bh[4][2], bl[4][2];
            #pragma unroll
            for (int nt = 0; nt < 4; nt++) {
                int n  = wn * 32 + nt * 8 + g;
                int kr = kc * 8 + t;
                bh[nt][0] = __float_as_uint(BHf[kr * 136 + n]);
                bh[nt][1] = __float_as_uint(BHf[(kr + 4) * 136 + n]);
                bl[nt][0] = __float_as_uint(BLf[kr * 136 + n]);
                bl[nt][1] = __float_as_uint(BLf[(kr + 4) * 136 + n]);
            }
            #pragma unroll
            for (int mt = 0; mt < 2; mt++)
                #pragma unroll
                for (int nt = 0; nt < 4; nt++) {
                    mma_tf32(acc[mt][nt], ah[mt], bh[nt][0], bh[nt][1]);
                    mma_tf32(acc[mt][nt], al[mt], bh[nt][0], bh[nt][1]);
                    mma_tf32(acc[mt][nt], ah[mt], bl[nt][0], bl[nt][1]);
                }
        }
        __syncthreads();
        if (s + 2 < 18) issue(s + 2, buf);
    }

    #pragma unroll
    for (int mt = 0; mt < 2; mt++)
        #pragma unroll
        for (int nt = 0; nt < 4; nt++) {
            int r  = p0 + wm * 32 + mt * 16 + g;
            int cc = wn * 32 + nt * 8 + 2 * t;
            *(float2*)&g_x[(size_t)r * DD + cc]       = make_float2(acc[mt][nt][0], acc[mt][nt][1]);
            *(float2*)&g_x[(size_t)(r + 8) * DD + cc] = make_float2(acc[mt][nt][2], acc[mt][nt][3]);
        }
}

// ============================================================
// VQ approximate pass — round-8 v2 + BOOTSTRAPPED lagged threshold:
// iter 0: full global reduction (tight seed for thrS).
// iters >=1: thr = min(thrS_lagged[row], lm_local) + eb, 2 syncs/iter.
// Retention proof: threshold is subset-min + 2err + slack.
// ============================================================
#define LDB      272
#define A_OFF    0                       // 128 x 272 = 34816
#define B_OFF    34816                   // 2 x 34816
#define CNS_OFF  104448                  // 2 x 128 floats
#define EB2_OFF  105472                  // 128 floats
#define RMIN_OFF 105984                  // 4 x 128 floats
#define THR_OFF  108032                  // 128 floats (lagged global row min)
#define VQ_SMEM  108544
#define NIT 32

__device__ __forceinline__ void vq_loadB(uint32_t su, int buf, int kglob, int tid) {
    #pragma unroll
    for (int t = 0; t < 8; t++) {
        int j   = t * 256 + tid;
        int row = j >> 4;
        int c   = j & 15;
        cp16(su + B_OFF + buf * 34816 + row * LDB + c * 16,
             (const char*)g_cs + ((size_t)(kglob + row) * DD + c * 8) * 2);
    }
}

__global__ void __launch_bounds__(256, 2) k_vqtc() {
    extern __shared__ char smc[];
    uint32_t su = smem_u32(smc);
    int tid  = threadIdx.x;
    int wid  = tid >> 5;
    int lane = tid & 31;
    int wm   = wid & 1;
    int wn   = wid >> 1;
    int tt   = blockIdx.x >> 2;
    int sp   = blockIdx.x & 3;
    int kb0  = sp * 4096;

    float* cns  = (float*)(smc + CNS_OFF);
    float* eb2  = (float*)(smc + EB2_OFF);
    float* rmin = (float*)(smc + RMIN_OFF);
    float* thrS = (float*)(smc + THR_OFF);

    #pragma unroll
    for (int t = 0; t < 8; t++) {
        int i   = t * 256 + tid;
        int row = i >> 4;
        int c   = i & 15;
        cp16(su + A_OFF + row * LDB + c * 16,
             (const char*)g_xs + ((size_t)(tt * 128 + row) * DD + c * 8) * 2);
    }
    vq_loadB(su, 0, kb0, tid);
    CP_COMMIT();
    vq_loadB(su, 1, kb0 + 128, tid);
    CP_COMMIT();

    if (tid < 128) {
        cns[tid]       = g_cnorm[kb0 + tid];
        cns[128 + tid] = g_cnorm[kb0 + 128 + tid];
        float cmax = __int_as_float(g_cmax_bits);
        float xn = g_xnorm[tt * 128 + tid];
        eb2[tid]  = 2.f * (0.0041f * xn * cmax) + 0.1f;
        thrS[tid] = 1e30f;
    }
    CP_WAIT1();
    __syncthreads();

    uint32_t aBase = su + A_OFF + (wm * 64 + (lane & 15)) * LDB + (lane >> 4) * 16;
    uint32_t bBase = su + B_OFF + (wn * 32 + (lane & 15)) * LDB + (lane >> 4) * 16;

    for (int it = 0; it < NIT; it++) {
        int buf = it & 1;
        float acc[4][4][4];
        #pragma unroll
        for (int mt = 0; mt < 4; mt++)
            #pragma unroll
            for (int nt = 0; nt < 4; nt++)
                #pragma unroll
                for (int c = 0; c < 4; c++) acc[mt][nt][c] = 0.f;

        #pragma unroll
        for (int ks = 0; ks < 8; ks++) {
            uint32_t a[4][4];
            #pragma unroll
            for (int mt = 0; mt < 4; mt++)
                ldsm4(a[mt][0], a[mt][1], a[mt][2], a[mt][3],
                      aBase + mt * (16 * LDB) + ks * 32);
            uint32_t b0[4], b1[4];
            #pragma unroll
            for (int np = 0; np < 2; np++) {
                uint32_t r0, r1, r2, r3;
                ldsm4(r0, r1, r2, r3,
                      bBase + buf * 34816 + np * (16 * LDB) + ks * 32);
                b0[np * 2] = r0; b1[np * 2] = r2;
                b0[np * 2 + 1] = r1; b1[np * 2 + 1] = r3;
            }
            #pragma unroll
            for (int mt = 0; mt < 4; mt++)
                #pragma unroll
                for (int nt = 0; nt < 4; nt++)
                    mma16816(acc[mt][nt], a[mt], b0[nt], b1[nt]);
        }

        // per-thread row minima (8 row-slots)
        float lm[8];
        #pragma unroll
        for (int mt = 0; mt < 4; mt++) {
            #pragma unroll
            for (int h = 0; h < 2; h++) {
                float m = 1e30f;
                #pragma unroll
                for (int nt = 0; nt < 4; nt++) {
                    int colb = wn * 32 + nt * 8 + (lane & 3) * 2;
                    float s0 = cns[buf * 128 + colb]     - acc[mt][nt][h * 2];
                    float s1 = cns[buf * 128 + colb + 1] - acc[mt][nt][h * 2 + 1];
                    m = fminf(m, fminf(s0, s1));
                }
                lm[mt * 2 + h] = m;
            }
        }
        #pragma unroll
        for (int s = 0; s < 8; s++) {
            lm[s] = fminf(lm[s], __shfl_xor_sync(0xffffffffu, lm[s], 1));
            lm[s] = fminf(lm[s], __shfl_xor_sync(0xffffffffu, lm[s], 2));
        }
        if ((lane & 3) == 0) {
            #pragma unroll
            for (int mt = 0; mt < 4; mt++)
                #pragma unroll
                for (int h = 0; h < 2; h++) {
                    int row = wm * 64 + mt * 16 + (lane >> 2) + h * 8;
                    rmin[wn * 128 + row] = lm[mt * 2 + h];
                }
        }

        if (it == 0) {
            // bootstrap: full reduction before collect (tight seed)
            __syncthreads();
            if (tid < 128) {
                float r = fminf(fminf(rmin[tid], rmin[128 + tid]),
                                fminf(rmin[256 + tid], rmin[384 + tid]));
                thrS[tid] = r;
            }
            __syncthreads();
        }

        // candidate collection (iter0: thrS = current global; else lagged)
        #pragma unroll
        for (int mt = 0; mt < 4; mt++) {
            #pragma unroll
            for (int h = 0; h < 2; h++) {
                int row = wm * 64 + mt * 16 + (lane >> 2) + h * 8;
                float thrv = fminf(thrS[row], lm[mt * 2 + h]) + eb2[row];
                if (lm[mt * 2 + h] < thrv) {
                    int tok = tt * 128 + row;
                    #pragma unroll
                    for (int nt = 0; nt < 4; nt++) {
                        int colb = wn * 32 + nt * 8 + (lane & 3) * 2;
                        #pragma unroll
                        for (int cc = 0; cc < 2; cc++) {
                            float sc = cns[buf * 128 + colb + cc] - acc[mt][nt][h * 2 + cc];
                            if (sc < thrv) {
                                int pos = atomicAdd(&g_ccount[tok], 1);
                                if (pos < CAP)
                                    g_cand[tok * CAP + pos] = kb0 + it * 128 + colb + cc;
                            }
                        }
                    }
                }
            }
        }
        __syncthreads();   // B[buf]/cns[buf] reads done; rmin writes visible

        // publish global row min (lagged by one iter)
        if (tid < 128) {
            float r = fminf(fminf(rmin[tid], rmin[128 + tid]),
                            fminf(rmin[256 + tid], rmin[384 + tid]));
            thrS[tid] = fminf(thrS[tid], r);
        }
        if (it + 2 < NIT) {
            vq_loadB(su, buf, kb0 + (it + 2) * 128, tid);
            CP_COMMIT();
            if (tid < 128) cns[buf * 128 + tid] = g_cnorm[kb0 + (it + 2) * 128 + tid];
        }
        if (it + 1 < NIT) {
            if (it + 2 < NIT) { CP_WAIT1(); } else { CP_WAIT0(); }
            __syncthreads();   // thrS/cns writes visible; smem loads landed
        }
    }
}

// ============================================================
// Fused exact fp32 re-rank + NSVQ post (one warp per token)
// ============================================================
__global__ void k_respost(const float* __restrict__ cb, const float* __restrict__ rv) {
    int gw   = (blockIdx.x * blockDim.x + threadIdx.x) >> 5;
    int lane = threadIdx.x & 31;
    if (gw >= NN) return;
    int cnt = g_ccount[gw];
    const float* xp = g_x + (size_t)gw * DD;
    float x4[4];
    #pragma unroll
    for (int t = 0; t < 4; t++) x4[t] = xp[lane + t * 32];

    float bestv = 1e30f;
    int   bestk = KB;

    if (cnt <= CAP) {
        for (int i = 0; i < cnt; i++) {
            int k = g_cand[gw * CAP + i];
            const float* cp = cb + (size_t)k * DD;
            float p = 0.f;
            #pragma unroll
            for (int t = 0; t < 4; t++) p = fmaf(x4[t], cp[lane + t * 32], p);
            #pragma unroll
            for (int o = 16; o; o >>= 1) p += __shfl_xor_sync(0xffffffffu, p, o);
            float sc = g_cnorm[k] - p;
            if (sc < bestv || (sc == bestv && k < bestk)) { bestv = sc; bestk = k; }
        }
    } else {
        for (int k = lane; k < KB; k += 32) {
            const float* cp = cb + (size_t)k * DD;
            float p = 0.f;
            for (int d = 0; d < DD; d++) p = fmaf(__ldg(xp + d), __ldg(cp + d), p);
            float sc = g_cnorm[k] - p;
            if (sc < bestv || (sc == bestv && k < bestk)) { bestv = sc; bestk = k; }
        }
        #pragma unroll
        for (int o = 16; o; o >>= 1) {
            float ov = __shfl_down_sync(0xffffffffu, bestv, o);
            int   ok = __shfl_down_sync(0xffffffffu, bestk, o);
            if (ov < bestv || (ov == bestv && ok < bestk)) { bestv = ov; bestk = ok; }
        }
        bestk = __shfl_sync(0xffffffffu, bestk, 0);
    }

    const float* cp = cb + (size_t)bestk * DD;
    const float* rp = rv + (size_t)gw * DD;
    float rr[4];
    float sr = 0.f, sn = 0.f;
    #pragma unroll
    for (int t = 0; t < 4; t++) {
        int d = lane + t * 32;
        float cv = cp[d], rvv = rp[d];
        rr[t] = rvv;
        float df = x4[t] - cv;
        sr += df * df;
        sn += rvv * rvv;
    }
    #pragma unroll
    for (int o = 16; o; o >>= 1) {
        sr += __shfl_xor_sync(0xffffffffu, sr, o);
        sn += __shfl_xor_sync(0xffffffffu, sn, o);
    }
    float ratio = sqrtf(sr) / sqrtf(sn) + 1e-12f;
    float* qp = g_q + (size_t)gw * DD;
    #pragma unroll
    for (int t = 0; t < 4; t++) qp[lane + t * 32] = x4[t] + ratio * rr[t];
    if (lane == 0) {
        g_idx[gw] = bestk;
        atomicAdd(&g_counts[bestk], 1.0f);
    }
}

// ============================================================
// Final scalars (unchanged)
// ============================================================
__global__ void k_final(const int* __restrict__ used, float* __restrict__ out) {
    __shared__ float red[256];
    int tid = threadIdx.x;
    float s = 0.f;
    for (int k = tid; k < KB; k += 256) {
        float p = g_counts[k] * (1.0f / 8192.0f);
        s += p * logf(p + 1e-12f);
    }
    red[tid] = s;
    __syncthreads();
    for (int o = 128; o; o >>= 1) {
        if (tid < o) red[tid] += red[tid + o];
        __syncthreads();
    }
    if (tid == 0) out[4194304] = expf(-red[0]);
    for (int k = tid; k < KB; k += 256)
        out[4194305 + k] = (float)(used[k] + (int)g_counts[k]);
    for (int n = tid; n < NN; n += 256)
        out[4194305 + KB + n] = (float)g_idx[n];
}

// ============================================================
// Decode GEMM via 3xTF32 (keep)
// ============================================================
#define DEC_SMEM 104448
__global__ void __launch_bounds__(256, 1) k_dec(const float* __restrict__ bout,
                                                float* __restrict__ out) {
    extern __shared__ char smc[];
    float*   fs = (float*)smc;
    uint32_t su = smem_u32(smc);
    int tid  = threadIdx.x;
    int wid  = tid >> 5;
    int lane = tid & 31;
    int g    = lane >> 2;
    int t    = lane & 3;
    int wm   = wid & 3;
    int wn   = wid >> 2;
    int m0   = (blockIdx.x >> 2) * 128;
    int n0   = (blockIdx.x & 3) * 128;
    int bg0  = m0 >> 6;

    float acc[2][8][4];
    #pragma unroll
    for (int i = 0; i < 2; i++)
        #pragma unroll
        for (int j = 0; j < 8; j++)
            #pragma unroll
            for (int c = 0; c < 4; c++) acc[i][j][c] = 0.f;

    auto issue = [&](int ch, int buf) {
        int k0 = ch * 32;
        #pragma unroll
        for (int it = 0; it < 4; it++) {
            int idx = it * 256 + tid;
            int d   = idx >> 5;
            int r   = idx & 31;
            int bgl = r >> 4;
            int j4  = r & 15;
            cp16(su + buf * 17408 + d * 544 + bgl * 256 + j4 * 16,
                 g_q + (size_t)(bg0 + bgl) * 8192 + (size_t)(k0 + d) * 64 + j4 * 4);
        }
        #pragma unroll
        for (int it = 0; it < 4; it++) {
            int idx = it * 256 + tid;
            int row = idx >> 5;
            int c   = idx & 31;
            cp16(su + 34816 + buf * 17408 + row * 544 + c * 16,
                 g_ohi + (size_t)(k0 + row) * DIMI + n0 + c * 4);
            cp16(su + 69632 + buf * 17408 + row * 544 + c * 16,
                 g_olo + (size_t)(k0 + row) * DIMI + n0 + c * 4);
        }
        CP_COMMIT();
    };

    issue(0, 0);
    issue(1, 1);

    for (int ch = 0; ch < 4; ch++) {
        int buf = ch & 1;
        if (ch < 3) { CP_WAIT1(); } else { CP_WAIT0(); }
        __syncthreads();

        const float* Af  = fs + buf * 4352;
        const float* BHf = fs + 8704 + buf * 4352;
        const float* BLf = fs + 17408 + buf * 4352;

        #pragma unroll
        for (int kc = 0; kc < 4; kc++) {
            uint32_t ah[2][4], al[2][4];
            #pragma unroll
            for (int mt = 0; mt < 2; mt++) {
                int r0 = wm * 32 + mt * 16 + g;
                int c0 = kc * 8 + t;
                float d0 = Af[c0 * 136 + r0];
                float d1 = Af[c0 * 136 + r0 + 8];
                float d2 = Af[(c0 + 4) * 136 + r0];
                float d3 = Af[(c0 + 4) * 136 + r0 + 8];
                tf32split(d0, ah[mt][0], al[mt][0]);
                tf32split(d1, ah[mt][1], al[mt][1]);
                tf32split(d2, ah[mt][2], al[mt][2]);
                tf32split(d3, ah[mt][3], al[mt][3]);
            }
            uint32_t bh[8][2], bl[8][2];
            #pragma unroll
            for (int nt = 0; nt < 8; nt++) {
                int n  = wn * 64 + nt * 8 + g;
                int kr = kc * 8 + t;
                bh[nt][0] = __float_as_uint(BHf[kr * 136 + n]);
                bh[nt][1] = __float_as_uint(BHf[(kr + 4) * 136 + n]);
                bl[nt][0] = __float_as_uint(BLf[kr * 136 + n]);
                bl[nt][1] = __float_as_uint(BLf[(kr + 4) * 136 + n]);
            }
            #pragma unroll
            for (int mt = 0; mt < 2; mt++)
                #pragma unroll
                for (int nt = 0; nt < 8; nt++) {
                    mma_tf32(acc[mt][nt], ah[mt], bh[nt][0], bh[nt][1]);
                    mma_tf32(acc[mt][nt], al[mt], bh[nt][0], bh[nt][1]);
                    mma_tf32(acc[mt][nt], ah[mt], bl[nt][0], bl[nt][1]);
                }
        }
        __syncthreads();
        if (ch + 2 < 4) issue(ch + 2, buf);
    }

    #pragma unroll
    for (int mt = 0; mt < 2; mt++)
        #pragma unroll
        for (int nt = 0; nt < 8; nt++) {
            int r  = m0 + wm * 32 + mt * 16 + g;
            int cc = n0 + wn * 64 + nt * 8 + 2 * t;
            float2 bb = *(const float2*)&bout[cc];
            *(float2*)&out[(size_t)r * DIMI + cc] =
                make_float2(acc[mt][nt][0] + bb.x, acc[mt][nt][1] + bb.y);
            *(float2*)&out[(size_t)(r + 8) * DIMI + cc] =
                make_float2(acc[mt][nt][2] + bb.x, acc[mt][nt][3] + bb.y);
        }
}

// ============================================================
// Launcher: round-10 fork-join stream overlap (passing).
// ============================================================
extern "C" void kernel_launch(void* const* d_in, const int* in_sizes, int n_in,
                              void* d_out, int out_size) {
    (void)in_sizes; (void)n_in; (void)out_size;
    const float* in_f   = (const float*)d_in[0];
    const float* in_l   = (const float*)d_in[1];
    const float* rv     = (const float*)d_in[2];
    const float* cb     = (const float*)d_in[3];
    const float* W_in   = (const float*)d_in[4];
    const float* conv_w = (const float*)d_in[6];
    const float* W_out  = (const float*)d_in[8];
    const float* b_out  = (const float*)d_in[9];
    const int*   used   = (const int*)d_in[10];
    float* out = (float*)d_out;

    cudaFuncSetAttribute(k_vqtc,  cudaFuncAttributeMaxDynamicSharedMemorySize, VQ_SMEM);
    cudaFuncSetAttribute(k_gemm1, cudaFuncAttributeMaxDynamicSharedMemorySize, G1_SMEM);
    cudaFuncSetAttribute(k_conv,  cudaFuncAttributeMaxDynamicSharedMemorySize, CV_SMEM);
    cudaFuncSetAttribute(k_dec,   cudaFuncAttributeMaxDynamicSharedMemorySize, DEC_SMEM);

    cudaStream_t s1;
    cudaStreamCreateWithFlags(&s1, cudaStreamNonBlocking);
    cudaEvent_t eFork, ePrep, eRes, eJoin;
    cudaEventCreateWithFlags(&eFork, cudaEventDisableTiming);
    cudaEventCreateWithFlags(&ePrep, cudaEventDisableTiming);
    cudaEventCreateWithFlags(&eRes,  cudaEventDisableTiming);
    cudaEventCreateWithFlags(&eJoin, cudaEventDisableTiming);

    // fork: codebook + conv-weight prep on side stream, overlapped with gemm1
    cudaEventRecord(eFork, 0);
    cudaStreamWaitEvent(s1, eFork, 0);
    k_prep_c <<<576, 256, 0, s1>>>(conv_w);
    k_cbprep <<<2048, 256, 0, s1>>>(cb);
    cudaEventRecord(ePrep, s1);

    // main chain
    k_prep_wo<<<512, 256>>>(W_in, W_out);
    k_gemm1  <<<256, 256, G1_SMEM>>>(in_l, in_f);
    cudaStreamWaitEvent(0, ePrep, 0);       // conv needs g_wthi/g_wtlo
    k_conv   <<<128, 256, CV_SMEM>>>();
    k_splitx <<<1024, 256>>>();
    k_vqtc   <<<256, 256, VQ_SMEM>>>();
    k_respost<<<1024, 256>>>(cb, rv);

    // fork: final (scalars/tail of out) overlapped with decode GEMM
    cudaEventRecord(eRes, 0);
    cudaStreamWaitEvent(s1, eRes, 0);
    k_final  <<<1, 256, 0, s1>>>(used, out);
    k_dec    <<<256, 256, DEC_SMEM>>>(b_out, out);

    // join side stream back before returning (capture requirement)
    cudaEventRecord(eJoin, s1);
    cudaStreamWaitEvent(0, eJoin, 0);
}

// round 13
// speedup vs baseline: 8.6808x; 1.0120x over previous
#include <cuda_runtime.h>
#include <cuda_bf16.h>
#include <math.h>
#include <stdint.h>

// ---------------- problem dims ----------------
#define KB   16384
#define NN   8192
#define M1   32768
#define DD   128
#define DIMI 512
#define CAP  64

// ---------------- scratch ----------------
__device__ float g_h[M1 * DD];
__device__ float g_x[NN * DD];
__device__ float g_q[NN * DD];
__device__ float g_cnorm[KB];
__device__ float g_counts[KB];
__device__ int   g_idx[NN];
__device__ __nv_bfloat16 g_xs[NN * DD];           // x hi (bf16)
__device__ __nv_bfloat16 g_cs[(size_t)KB * DD];   // codebook hi (bf16)
__device__ float g_xnorm[NN];                     // |x|^2 (accumulated by conv)
__device__ int   g_cmax_bits;
__device__ int   g_ccount[NN];
__device__ int   g_cand[NN * CAP];
// tf32-split weights
__device__ float g_whi[DIMI * DD];                // W_in hi  [k][n]
__device__ float g_wlo[DIMI * DD];
__device__ float g_wthi[9 * DD * DD];             // conv w hi [kk][din][dout]
__device__ float g_wtlo[9 * DD * DD];
__device__ float g_ohi[DD * DIMI];                // W_out hi [k][n]
__device__ float g_olo[DD * DIMI];

// ---------------- helpers ----------------
__device__ __forceinline__ uint32_t smem_u32(const void* p) {
    uint32_t a;
    asm("{ .reg .u64 t; cvta.to.shared.u64 t, %1; cvt.u32.u64 %0, t; }" : "=r"(a) : "l"(p));
    return a;
}
__device__ __forceinline__ void cp16(uint32_t dst, const void* src) {
    asm volatile("cp.async.cg.shared.global [%0], [%1], 16;\n" :: "r"(dst), "l"(src));
}
__device__ __forceinline__ void cp16z(uint32_t dst, const void* src, int sz) {
    asm volatile("cp.async.cg.shared.global [%0], [%1], 16, %2;\n" :: "r"(dst), "l"(src), "r"(sz));
}
#define CP_COMMIT()  asm volatile("cp.async.commit_group;\n" ::: "memory")
#define CP_WAIT0()   asm volatile("cp.async.wait_group 0;\n" ::: "memory")
#define CP_WAIT1()   asm volatile("cp.async.wait_group 1;\n" ::: "memory")

__device__ __forceinline__ void ldsm4(uint32_t& r0, uint32_t& r1, uint32_t& r2, uint32_t& r3,
                                      uint32_t a) {
    asm volatile("ldmatrix.sync.aligned.m8n8.x4.shared.b16 {%0,%1,%2,%3}, [%4];"
                 : "=r"(r0), "=r"(r1), "=r"(r2), "=r"(r3) : "r"(a));
}
__device__ __forceinline__ void mma16816(float* d, const uint32_t* a, uint32_t b0, uint32_t b1) {
    asm volatile("mma.sync.aligned.m16n8k16.row.col.f32.bf16.bf16.f32 "
                 "{%0,%1,%2,%3}, {%4,%5,%6,%7}, {%8,%9}, {%0,%1,%2,%3};"
                 : "+f"(d[0]), "+f"(d[1]), "+f"(d[2]), "+f"(d[3])
                 : "r"(a[0]), "r"(a[1]), "r"(a[2]), "r"(a[3]), "r"(b0), "r"(b1));
}
__device__ __forceinline__ void mma_tf32(float* d, const uint32_t* a, uint32_t b0, uint32_t b1) {
    asm volatile("mma.sync.aligned.m16n8k8.row.col.f32.tf32.tf32.f32 "
                 "{%0,%1,%2,%3}, {%4,%5,%6,%7}, {%8,%9}, {%0,%1,%2,%3};"
                 : "+f"(d[0]), "+f"(d[1]), "+f"(d[2]), "+f"(d[3])
                 : "r"(a[0]), "r"(a[1]), "r"(a[2]), "r"(a[3]), "r"(b0), "r"(b1));
}
__device__ __forceinline__ void tf32split(float a, uint32_t& hi, uint32_t& lo) {
    asm("cvt.rna.tf32.f32 %0, %1;" : "=r"(hi) : "f"(a));
    float lof = a - __uint_as_float(hi);
    asm("cvt.rna.tf32.f32 %0, %1;" : "=r"(lo) : "f"(lof));
}
__device__ __forceinline__ uint32_t pack_bf16x2(float a, float b) {
    unsigned short s0 = __bfloat16_as_ushort(__float2bfloat16(a));
    unsigned short s1 = __bfloat16_as_ushort(__float2bfloat16(b));
    return (uint32_t)s0 | ((uint32_t)s1 << 16);
}

// ============================================================
// Prep: conv weight transpose + tf32 split (also resets cmax)
// ============================================================
__global__ void k_prep_c(const float* __restrict__ cw) {
    int i = blockIdx.x * 256 + threadIdx.x;
    if (i == 0) g_cmax_bits = 0;
    if (i < 9 * DD * DD) {
        int dout = i & 127;
        int din  = (i >> 7) & 127;
        int kk   = i >> 14;
        float w = cw[(dout * DD + din) * 9 + kk];
        uint32_t hi, lo;
        tf32split(w, hi, lo);
        g_wthi[kk * (DD * DD) + din * DD + dout] = __uint_as_float(hi);
        g_wtlo[kk * (DD * DD) + din * DD + dout] = __uint_as_float(lo);
    }
}
__global__ void k_prep_wo(const float* __restrict__ W, const float* __restrict__ Wout) {
    int i = blockIdx.x * 256 + threadIdx.x;
    if (i < DIMI * DD) {
        uint32_t hi, lo;
        tf32split(W[i], hi, lo);
        g_whi[i] = __uint_as_float(hi);
        g_wlo[i] = __uint_as_float(lo);
    } else if (i < 2 * DIMI * DD) {
        int j = i - DIMI * DD;
        uint32_t hi, lo;
        tf32split(Wout[j], hi, lo);
        g_ohi[j] = __uint_as_float(hi);
        g_olo[j] = __uint_as_float(lo);
    }
}

// ============================================================
// Codebook prep fused: cnorm + bf16 split + counter/norm zero
// ============================================================
__global__ void k_cbprep(const float* __restrict__ cb) {
    int k    = blockIdx.x * 8 + (threadIdx.x >> 5);
    int lane = threadIdx.x & 31;
    float4 v = ((const float4*)(cb + (size_t)k * DD))[lane];
    float s = v.x * v.x + v.y * v.y + v.z * v.z + v.w * v.w;
    uint2 u;
    u.x = pack_bf16x2(v.x, v.y);
    u.y = pack_bf16x2(v.z, v.w);
    ((uint2*)(g_cs + (size_t)k * DD))[lane] = u;
    #pragma unroll
    for (int o = 16; o; o >>= 1) s += __shfl_xor_sync(0xffffffffu, s, o);
    if (lane == 0) {
        g_cnorm[k]  = 0.5f * s;
        g_counts[k] = 0.f;
        if (k < NN) { g_ccount[k] = 0; g_xnorm[k] = 0.f; }
        atomicMax(&g_cmax_bits, __float_as_int(sqrtf(s)));
    }
}

// ============================================================
// GEMM1 via 3xTF32 — round-8 v1 (measured 89us). M tile 128.
// ============================================================
#define G1_SMEM 143360
__global__ void __launch_bounds__(256, 1) k_gemm1(const float* __restrict__ A1,
                                                  const float* __restrict__ A0) {
    extern __shared__ char smc[];
    float*   fs = (float*)smc;
    uint32_t su = smem_u32(smc);
    int tid  = threadIdx.x;
    int wid  = tid >> 5;
    int lane = tid & 31;
    int g    = lane >> 2;
    int t    = lane & 3;
    int wm   = wid & 3;
    int wn   = wid >> 2;
    int m0   = blockIdx.x * 128;

    float acc[2][8][4];
    #pragma unroll
    for (int i = 0; i < 2; i++)
        #pragma unroll
        for (int j = 0; j < 8; j++)
            #pragma unroll
            for (int c = 0; c < 4; c++) acc[i][j][c] = 0.f;

    auto issue = [&](int ch, int buf) {
        int k0 = ch * 32;
        #pragma unroll
        for (int it = 0; it < 4; it++) {
            int idx = it * 256 + tid;
            int row = idx >> 3;
            int c4  = idx & 7;
            cp16(su + buf * 18432 + row * 144 + c4 * 16,
                 A1 + (size_t)(m0 + row) * DIMI + k0 + c4 * 4);
            cp16(su + 36864 + buf * 18432 + row * 144 + c4 * 16,
                 A0 + (size_t)(m0 + row) * DIMI + k0 + c4 * 4);
        }
        #pragma unroll
        for (int it = 0; it < 4; it++) {
            int idx = it * 256 + tid;
            int row = idx >> 5;
            int c   = idx & 31;
            cp16(su + 73728 + buf * 17408 + row * 544 + c * 16,
                 g_whi + (size_t)(k0 + row) * DD + c * 4);
            cp16(su + 108544 + buf * 17408 + row * 544 + c * 16,
                 g_wlo + (size_t)(k0 + row) * DD + c * 4);
        }
        CP_COMMIT();
    };

    issue(0, 0);
    issue(1, 1);

    for (int ch = 0; ch < 16; ch++) {
        int buf = ch & 1;
        if (ch < 15) { CP_WAIT1(); } else { CP_WAIT0(); }
        __syncthreads();

        const float* A1f = fs + buf * 4608;
        const float* A0f = fs + 9216 + buf * 4608;
        const float* BHf = fs + 18432 + buf * 4352;
        const float* BLf = fs + 27136 + buf * 4352;

        #pragma unroll
        for (int kc = 0; kc < 4; kc++) {
            uint32_t ah[2][4], al[2][4];
            #pragma unroll
            for (int mt = 0; mt < 2; mt++) {
                int r0 = wm * 32 + mt * 16 + g;
                int c0 = kc * 8 + t;
                float d0 = A1f[r0 * 36 + c0]           - A0f[r0 * 36 + c0];
                float d1 = A1f[(r0 + 8) * 36 + c0]     - A0f[(r0 + 8) * 36 + c0];
                float d2 = A1f[r0 * 36 + c0 + 4]       - A0f[r0 * 36 + c0 + 4];
                float d3 = A1f[(r0 + 8) * 36 + c0 + 4] - A0f[(r0 + 8) * 36 + c0 + 4];
                tf32split(d0, ah[mt][0], al[mt][0]);
                tf32split(d1, ah[mt][1], al[mt][1]);
                tf32split(d2, ah[mt][2], al[mt][2]);
                tf32split(d3, ah[mt][3], al[mt][3]);
            }
            uint32_t bh[8][2], bl[8][2];
            #pragma unroll
            for (int nt = 0; nt < 8; nt++) {
                int n  = wn * 64 + nt * 8 + g;
                int kr = kc * 8 + t;
                bh[nt][0] = __float_as_uint(BHf[kr * 136 + n]);
                bh[nt][1] = __float_as_uint(BHf[(kr + 4) * 136 + n]);
                bl[nt][0] = __float_as_uint(BLf[kr * 136 + n]);
                bl[nt][1] = __float_as_uint(BLf[(kr + 4) * 136 + n]);
            }
            #pragma unroll
            for (int mt = 0; mt < 2; mt++)
                #pragma unroll
                for (int nt = 0; nt < 8; nt++) {
                    mma_tf32(acc[mt][nt], ah[mt], bh[nt][0], bh[nt][1]);
                    mma_tf32(acc[mt][nt], al[mt], bh[nt][0], bh[nt][1]);
                    mma_tf32(acc[mt][nt], ah[mt], bl[nt][0], bl[nt][1]);
                }
        }
        __syncthreads();
        if (ch + 2 < 16) issue(ch + 2, buf);
    }

    #pragma unroll
    for (int mt = 0; mt < 2; mt++)
        #pragma unroll
        for (int nt = 0; nt < 8; nt++) {
            int r  = m0 + wm * 32 + mt * 16 + g;
            int cc = wn * 64 + nt * 8 + 2 * t;
            *(float2*)&g_h[(size_t)r * DD + cc]       = make_float2(acc[mt][nt][0], acc[mt][nt][1]);
            *(float2*)&g_h[(size_t)(r + 8) * DD + cc] = make_float2(acc[mt][nt][2], acc[mt][nt][3]);
        }
}

// ============================================================
// Conv via 3xTF32 + FUSED splitx epilogue:
// writes g_x (fp32), g_xs (bf16) and accumulates g_xnorm (|x|^2)
// straight from the accumulators.
// ============================================================
#define CV_SMEM 174080
__global__ void __launch_bounds__(256, 1) k_conv() {
    extern __shared__ char smc[];
    float*   fs = (float*)smc;
    uint32_t su = smem_u32(smc);
    int tid  = threadIdx.x;
    int wid  = tid >> 5;
    int lane = tid & 31;
    int g    = lane >> 2;
    int t    = lane & 3;
    int wm   = wid & 1;
    int wn   = wid >> 1;
    int p0   = blockIdx.x * 64;

    float acc[2][4][4];
    #pragma unroll
    for (int i = 0; i < 2; i++)
        #pragma unroll
        for (int j = 0; j < 4; j++)
            #pragma unroll
            for (int c = 0; c < 4; c++) acc[i][j][c] = 0.f;

    auto issue = [&](int s, int buf) {
        int kk = s >> 1;
        int ch = s & 1;
        int kh = kk / 3, kw = kk % 3;
        #pragma unroll
        for (int it = 0; it < 4; it++) {
            int idx = it * 256 + tid;
            int pl  = idx >> 4;
            int cf  = idx & 15;
            int p  = p0 + pl;
            int b  = p >> 6;
            int jj = p & 63;
            int oh = jj >> 3, ow = jj & 7;
            int ih = 2 * oh - 1 + kh;
            int iw = 2 * ow - 1 + kw;
            bool valid = ((unsigned)ih < 16u) && ((unsigned)iw < 16u);
            const float* src = valid
                ? g_h + ((size_t)(b * 256 + ih * 16 + iw) * DD + ch * 64 + cf * 4)
                : g_h;
            cp16z(su + buf * 17408 + pl * 272 + cf * 16, src, valid ? 16 : 0);
        }
        #pragma unroll
        for (int it = 0; it < 8; it++) {
            int idx = it * 256 + tid;
            int row = idx >> 5;
            int c   = idx & 31;
            size_t so = (size_t)kk * (DD * DD) + (size_t)(ch * 64 + row) * DD + c * 4;
            cp16(su + 34816 + buf * 34816 + row * 544 + c * 16, g_wthi + so);
            cp16(su + 104448 + buf * 34816 + row * 544 + c * 16, g_wtlo + so);
        }
        CP_COMMIT();
    };

    issue(0, 0);
    issue(1, 1);

    for (int s = 0; s < 18; s++) {
        int buf = s & 1;
        if (s < 17) { CP_WAIT1(); } else { CP_WAIT0(); }
        __syncthreads();

        const float* Af  = fs + buf * 4352;
        const float* BHf = fs + 8704 + buf * 8704;
        const float* BLf = fs + 26112 + buf * 8704;

        #pragma unroll
        for (int kc = 0; kc < 8; kc++) {
            uint32_t ah[2][4], al[2][4];
            #pragma unroll
            for (int mt = 0; mt < 2; mt++) {
                int r0 = wm * 32 + mt * 16 + g;
                int c0 = kc * 8 + t;
                tf32split(Af[r0 * 68 + c0],           ah[mt][0], al[mt][0]);
                tf32split(Af[(r0 + 8) * 68 + c0],     ah[mt][1], al[mt][1]);
                tf32split(Af[r0 * 68 + c0 + 4],       ah[mt][2], al[mt][2]);
                tf32split(Af[(r0 + 8) * 68 + c0 + 4], ah[mt][3], al[mt][3]);
            }
            uint32_t bh[4][2], bl[4][2];
            #pragma unroll
            for (int nt = 0; nt < 4; nt++) {
                int n  = wn * 32 + nt * 8 + g;
                int kr = kc * 8 + t;
                bh[nt][0] = __float_as_uint(BHf[kr * 136 + n]);
                bh[nt][1] = __float_as_uint(BHf[(kr + 4) * 136 + n]);
                bl[nt][0] = __float_as_uint(BLf[kr * 136 + n]);
                bl[nt][1] = __float_as_uint(BLf[(kr + 4) * 136 + n]);
            }
            #pragma unroll
            for (int mt = 0; mt < 2; mt++)
                #pragma unroll
                for (int nt = 0; nt < 4; nt++) {
                    mma_tf32(acc[mt][nt], ah[mt], bh[nt][0], bh[nt][1]);
                    mma_tf32(acc[mt][nt], al[mt], bh[nt][0], bh[nt][1]);
                    mma_tf32(acc[mt][nt], ah[mt], bl[nt][0], bl[nt][1]);
                }
        }
        __syncthreads();
        if (s + 2 < 18) issue(s + 2, buf);
    }

    // fused epilogue: g_x (fp32) + g_xs (bf16) + |x|^2 accumulation
    float sq0[2] = {0.f, 0.f};   // row r, per mt
    float sq1[2] = {0.f, 0.f};   // row r+8
    #pragma unroll
    for (int mt = 0; mt < 2; mt++) {
        #pragma unroll
        for (int nt = 0; nt < 4; nt++) {
            int r  = p0 + wm * 32 + mt * 16 + g;
            int cc = wn * 32 + nt * 8 + 2 * t;
            float a0 = acc[mt][nt][0], a1 = acc[mt][nt][1];
            float a2 = acc[mt][nt][2], a3 = acc[mt][nt][3];
            *(float2*)&g_x[(size_t)r * DD + cc]       = make_float2(a0, a1);
            *(float2*)&g_x[(size_t)(r + 8) * DD + cc] = make_float2(a2, a3);
            *(uint32_t*)&g_xs[(size_t)r * DD + cc]       = pack_bf16x2(a0, a1);
            *(uint32_t*)&g_xs[(size_t)(r + 8) * DD + cc] = pack_bf16x2(a2, a3);
            sq0[mt] += a0 * a0 + a1 * a1;
            sq1[mt] += a2 * a2 + a3 * a3;
        }
    }
    #pragma unroll
    for (int mt = 0; mt < 2; mt++) {
        sq0[mt] += __shfl_xor_sync(0xffffffffu, sq0[mt], 1);
        sq0[mt] += __shfl_xor_sync(0xffffffffu, sq0[mt], 2);
        sq1[mt] += __shfl_xor_sync(0xffffffffu, sq1[mt], 1);
        sq1[mt] += __shfl_xor_sync(0xffffffffu, sq1[mt], 2);
        if (t == 0) {
            int r = p0 + wm * 32 + mt * 16 + g;
            atomicAdd(&g_xnorm[r], sq0[mt]);
            atomicAdd(&g_xnorm[r + 8], sq1[mt]);
        }
    }
}

// ============================================================
// VQ approximate pass — round-8 v2 (measured-best). 128-token tiles,
// 2 CTAs/SM, 8 warps = 2M(64 rows) x 4N(32 codes), smem row-min exchange.
// ============================================================
#define LDB      272
#define A_OFF    0                       // 128 x 272 = 34816
#define B_OFF    34816                   // 2 x 34816
#define CNS_OFF  104448                  // 2 x 128 floats
#define EB2_OFF  105472                  // 128 floats
#define RMIN_OFF 105984                  // 4 x 128 floats
#define RM_OFF   108032                  // 128 floats
#define VQ_SMEM  108544
#define NIT 32

__device__ __forceinline__ void vq_loadB(uint32_t su, int buf, int kglob, int tid) {
    #pragma unroll
    for (int t = 0; t < 8; t++) {
        int j   = t * 256 + tid;
        int row = j >> 4;
        int c   = j & 15;
        cp16(su + B_OFF + buf * 34816 + row * LDB + c * 16,
             (const char*)g_cs + ((size_t)(kglob + row) * DD + c * 8) * 2);
    }
}

__global__ void __launch_bounds__(256, 2) k_vqtc() {
    extern __shared__ char smc[];
    uint32_t su = smem_u32(smc);
    int tid  = threadIdx.x;
    int wid  = tid >> 5;
    int lane = tid & 31;
    int wm   = wid & 1;
    int wn   = wid >> 1;
    int tt   = blockIdx.x >> 2;
    int sp   = blockIdx.x & 3;
    int kb0  = sp * 4096;

    float* cns  = (float*)(smc + CNS_OFF);
    float* eb2  = (float*)(smc + EB2_OFF);
    float* rmin = (float*)(smc + RMIN_OFF);
    float* rm   = (float*)(smc + RM_OFF);

    #pragma unroll
    for (int t = 0; t < 8; t++) {
        int i   = t * 256 + tid;
        int row = i >> 4;
        int c   = i & 15;
        cp16(su + A_OFF + row * LDB + c * 16,
             (const char*)g_xs + ((size_t)(tt * 128 + row) * DD + c * 8) * 2);
    }
    vq_loadB(su, 0, kb0, tid);
    CP_COMMIT();
    vq_loadB(su, 1, kb0 + 128, tid);
    CP_COMMIT();

    if (tid < 128) {
        cns[tid]       = g_cnorm[kb0 + tid];
        cns[128 + tid] = g_cnorm[kb0 + 128 + tid];
        float cmax = __int_as_float(g_cmax_bits);
        float xn = sqrtf(g_xnorm[tt * 128 + tid]);
        eb2[tid] = 2.f * (0.0041f * xn * cmax) + 0.1f;
        rm[tid]  = 1e30f;
    }
    CP_WAIT1();
    __syncthreads();

    uint32_t aBase = su + A_OFF + (wm * 64 + (lane & 15)) * LDB + (lane >> 4) * 16;
    uint32_t bBase = su + B_OFF + (wn * 32 + (lane & 15)) * LDB + (lane >> 4) * 16;

    for (int it = 0; it < NIT; it++) {
        int buf = it & 1;
        float acc[4][4][4];
        #pragma unroll
        for (int mt = 0; mt < 4; mt++)
            #pragma unroll
            for (int nt = 0; nt < 4; nt++)
                #pragma unroll
                for (int c = 0; c < 4; c++) acc[mt][nt][c] = 0.f;

        #pragma unroll
        for (int ks = 0; ks < 8; ks++) {
            uint32_t a[4][4];
            #pragma unroll
            for (int mt = 0; mt < 4; mt++)
                ldsm4(a[mt][0], a[mt][1], a[mt][2], a[mt][3],
                      aBase + mt * (16 * LDB) + ks * 32);
            uint32_t b0[4], b1[4];
            #pragma unroll
            for (int np = 0; np < 2; np++) {
                uint32_t r0, r1, r2, r3;
                ldsm4(r0, r1, r2, r3,
                      bBase + buf * 34816 + np * (16 * LDB) + ks * 32);
                b0[np * 2] = r0; b1[np * 2] = r2;
                b0[np * 2 + 1] = r1; b1[np * 2 + 1] = r3;
            }
            #pragma unroll
            for (int mt = 0; mt < 4; mt++)
                #pragma unroll
                for (int nt = 0; nt < 4; nt++)
                    mma16816(acc[mt][nt], a[mt], b0[nt], b1[nt]);
        }

        // per-thread row minima (8 row-slots)
        float lm[8];
        #pragma unroll
        for (int mt = 0; mt < 4; mt++) {
            #pragma unroll
            for (int h = 0; h < 2; h++) {
                float m = 1e30f;
                #pragma unroll
                for (int nt = 0; nt < 4; nt++) {
                    int colb = wn * 32 + nt * 8 + (lane & 3) * 2;
                    float s0 = cns[buf * 128 + colb]     - acc[mt][nt][h * 2];
                    float s1 = cns[buf * 128 + colb + 1] - acc[mt][nt][h * 2 + 1];
                    m = fminf(m, fminf(s0, s1));
                }
                lm[mt * 2 + h] = m;
            }
        }
        #pragma unroll
        for (int s = 0; s < 8; s++) {
            lm[s] = fminf(lm[s], __shfl_xor_sync(0xffffffffu, lm[s], 1));
            lm[s] = fminf(lm[s], __shfl_xor_sync(0xffffffffu, lm[s], 2));
        }
        if ((lane & 3) == 0) {
            #pragma unroll
            for (int mt = 0; mt < 4; mt++)
                #pragma unroll
                for (int h = 0; h < 2; h++) {
                    int row = wm * 64 + mt * 16 + (lane >> 2) + h * 8;
                    rmin[wn * 128 + row] = lm[mt * 2 + h];
                }
        }
        __syncthreads();
        if (tid < 128) {
            float tm = fminf(fminf(rmin[tid], rmin[128 + tid]),
                             fminf(rmin[256 + tid], rmin[384 + tid]));
            float r  = fminf(rm[tid], tm);
            rm[tid]  = r;
            rmin[tid] = r + eb2[tid];   // reuse rmin[0..127] as thresholds
        }
        __syncthreads();

        // candidate collection
        #pragma unroll
        for (int mt = 0; mt < 4; mt++) {
            #pragma unroll
            for (int h = 0; h < 2; h++) {
                int row = wm * 64 + mt * 16 + (lane >> 2) + h * 8;
                float thrv = rmin[row];
                if (lm[mt * 2 + h] < thrv) {
                    int tok = tt * 128 + row;
                    #pragma unroll
                    for (int nt = 0; nt < 4; nt++) {
                        int colb = wn * 32 + nt * 8 + (lane & 3) * 2;
                        #pragma unroll
                        for (int cc = 0; cc < 2; cc++) {
                            float sc = cns[buf * 128 + colb + cc] - acc[mt][nt][h * 2 + cc];
                            if (sc < thrv) {
                                int pos = atomicAdd(&g_ccount[tok], 1);
                                if (pos < CAP)
                                    g_cand[tok * CAP + pos] = kb0 + it * 128 + colb + cc;
                            }
                        }
                    }
                }
            }
        }
        __syncthreads();

        if (it + 2 < NIT) {
            vq_loadB(su, buf, kb0 + (it + 2) * 128, tid);
            CP_COMMIT();
            if (tid < 128) cns[buf * 128 + tid] = g_cnorm[kb0 + (it + 2) * 128 + tid];
        }
        if (it + 1 < NIT) {
            if (it + 2 < NIT) { CP_WAIT1(); } else { CP_WAIT0(); }
            __syncthreads();
        }
    }
}

// ============================================================
// Fused exact fp32 re-rank + NSVQ post (one warp per token)
// ============================================================
__global__ void k_respost(const float* __restrict__ cb, const float* __restrict__ rv) {
    int gw   = (blockIdx.x * blockDim.x + threadIdx.x) >> 5;
    int lane = threadIdx.x & 31;
    if (gw >= NN) return;
    int cnt = g_ccount[gw];
    const float* xp = g_x + (size_t)gw * DD;
    float x4[4];
    #pragma unroll
    for (int t = 0; t < 4; t++) x4[t] = xp[lane + t * 32];

    float bestv = 1e30f;
    int   bestk = KB;

    if (cnt <= CAP) {
        for (int i = 0; i < cnt; i++) {
            int k = g_cand[gw * CAP + i];
            const float* cp = cb + (size_t)k * DD;
            float p = 0.f;
            #pragma unroll
            for (int t = 0; t < 4; t++) p = fmaf(x4[t], cp[lane + t * 32], p);
            #pragma unroll
            for (int o = 16; o; o >>= 1) p += __shfl_xor_sync(0xffffffffu, p, o);
            float sc = g_cnorm[k] - p;
            if (sc < bestv || (sc == bestv && k < bestk)) { bestv = sc; bestk = k; }
        }
    } else {
        for (int k = lane; k < KB; k += 32) {
            const float* cp = cb + (size_t)k * DD;
            float p = 0.f;
            for (int d = 0; d < DD; d++) p = fmaf(__ldg(xp + d), __ldg(cp + d), p);
            float sc = g_cnorm[k] - p;
            if (sc < bestv || (sc == bestv && k < bestk)) { bestv = sc; bestk = k; }
        }
        #pragma unroll
        for (int o = 16; o; o >>= 1) {
            float ov = __shfl_down_sync(0xffffffffu, bestv, o);
            int   ok = __shfl_down_sync(0xffffffffu, bestk, o);
            if (ov < bestv || (ov == bestv && ok < bestk)) { bestv = ov; bestk = ok; }
        }
        bestk = __shfl_sync(0xffffffffu, bestk, 0);
    }

    const float* cp = cb + (size_t)bestk * DD;
    const float* rp = rv + (size_t)gw * DD;
    float rr[4];
    float sr = 0.f, sn = 0.f;
    #pragma unroll
    for (int t = 0; t < 4; t++) {
        int d = lane + t * 32;
        float cv = cp[d], rvv = rp[d];
        rr[t] = rvv;
        float df = x4[t] - cv;
        sr += df * df;
        sn += rvv * rvv;
    }
    #pragma unroll
    for (int o = 16; o; o >>= 1) {
        sr += __shfl_xor_sync(0xffffffffu, sr, o);
        sn += __shfl_xor_sync(0xffffffffu, sn, o);
    }
    float ratio = sqrtf(sr) / sqrtf(sn) + 1e-12f;
    float* qp = g_q + (size_t)gw * DD;
    #pragma unroll
    for (int t = 0; t < 4; t++) qp[lane + t * 32] = x4[t] + ratio * rr[t];
    if (lane == 0) {
        g_idx[gw] = bestk;
        atomicAdd(&g_counts[bestk], 1.0f);
    }
}

// ============================================================
// Final scalars (unchanged)
// ============================================================
__global__ void k_final(const int* __restrict__ used, float* __restrict__ out) {
    __shared__ float red[256];
    int tid = threadIdx.x;
    float s = 0.f;
    for (int k = tid; k < KB; k += 256) {
        float p = g_counts[k] * (1.0f / 8192.0f);
        s += p * logf(p + 1e-12f);
    }
    red[tid] = s;
    __syncthreads();
    for (int o = 128; o; o >>= 1) {
        if (tid < o) red[tid] += red[tid + o];
        __syncthreads();
    }
    if (tid == 0) out[4194304] = expf(-red[0]);
    for (int k = tid; k < KB; k += 256)
        out[4194305 + k] = (float)(used[k] + (int)g_counts[k]);
    for (int n = tid; n < NN; n += 256)
        out[4194305 + KB + n] = (float)g_idx[n];
}

// ============================================================
// Decode GEMM via 3xTF32 (keep)
// ============================================================
#define DEC_SMEM 104448
__global__ void __launch_bounds__(256, 1) k_dec(const float* __restrict__ bout,
                                                float* __restrict__ out) {
    extern __shared__ char smc[];
    float*   fs = (float*)smc;
    uint32_t su = smem_u32(smc);
    int tid  = threadIdx.x;
    int wid  = tid >> 5;
    int lane = tid & 31;
    int g    = lane >> 2;
    int t    = lane & 3;
    int wm   = wid & 3;
    int wn   = wid >> 2;
    int m0   = (blockIdx.x >> 2) * 128;
    int n0   = (blockIdx.x & 3) * 128;
    int bg0  = m0 >> 6;

    float acc[2][8][4];
    #pragma unroll
    for (int i = 0; i < 2; i++)
        #pragma unroll
        for (int j = 0; j < 8; j++)
            #pragma unroll
            for (int c = 0; c < 4; c++) acc[i][j][c] = 0.f;

    auto issue = [&](int ch, int buf) {
        int k0 = ch * 32;
        #pragma unroll
        for (int it = 0; it < 4; it++) {
            int idx = it * 256 + tid;
            int d   = idx >> 5;
            int r   = idx & 31;
            int bgl = r >> 4;
            int j4  = r & 15;
            cp16(su + buf * 17408 + d * 544 + bgl * 256 + j4 * 16,
                 g_q + (size_t)(bg0 + bgl) * 8192 + (size_t)(k0 + d) * 64 + j4 * 4);
        }
        #pragma unroll
        for (int it = 0; it < 4; it++) {
            int idx = it * 256 + tid;
            int row = idx >> 5;
            int c   = idx & 31;
            cp16(su + 34816 + buf * 17408 + row * 544 + c * 16,
                 g_ohi + (size_t)(k0 + row) * DIMI + n0 + c * 4);
            cp16(su + 69632 + buf * 17408 + row * 544 + c * 16,
                 g_olo + (size_t)(k0 + row) * DIMI + n0 + c * 4);
        }
        CP_COMMIT();
    };

    issue(0, 0);
    issue(1, 1);

    for (int ch = 0; ch < 4; ch++) {
        int buf = ch & 1;
        if (ch < 3) { CP_WAIT1(); } else { CP_WAIT0(); }
        __syncthreads();

        const float* Af  = fs + buf * 4352;
        const float* BHf = fs + 8704 + buf * 4352;
        const float* BLf = fs + 17408 + buf * 4352;

        #pragma unroll
        for (int kc = 0; kc < 4; kc++) {
            uint32_t ah[2][4], al[2][4];
            #pragma unroll
            for (int mt = 0; mt < 2; mt++) {
                int r0 = wm * 32 + mt * 16 + g;
                int c0 = kc * 8 + t;
                float d0 = Af[c0 * 136 + r0];
                float d1 = Af[c0 * 136 + r0 + 8];
                float d2 = Af[(c0 + 4) * 136 + r0];
                float d3 = Af[(c0 + 4) * 136 + r0 + 8];
                tf32split(d0, ah[mt][0], al[mt][0]);
                tf32split(d1, ah[mt][1], al[mt][1]);
                tf32split(d2, ah[mt][2], al[mt][2]);
                tf32split(d3, ah[mt][3], al[mt][3]);
            }
            uint32_t bh[8][2], bl[8][2];
            #pragma unroll
            for (int nt = 0; nt < 8; nt++) {
                int n  = wn * 64 + nt * 8 + g;
                int kr = kc * 8 + t;
                bh[nt][0] = __float_as_uint(BHf[kr * 136 + n]);
                bh[nt][1] = __float_as_uint(BHf[(kr + 4) * 136 + n]);
                bl[nt][0] = __float_as_uint(BLf[kr * 136 + n]);
                bl[nt][1] = __float_as_uint(BLf[(kr + 4) * 136 + n]);
            }
            #pragma unroll
            for (int mt = 0; mt < 2; mt++)
                #pragma unroll
                for (int nt = 0; nt < 8; nt++) {
                    mma_tf32(acc[mt][nt], ah[mt], bh[nt][0], bh[nt][1]);
                    mma_tf32(acc[mt][nt], al[mt], bh[nt][0], bh[nt][1]);
                    mma_tf32(acc[mt][nt], ah[mt], bl[nt][0], bl[nt][1]);
                }
        }
        __syncthreads();
        if (ch + 2 < 4) issue(ch + 2, buf);
    }

    #pragma unroll
    for (int mt = 0; mt < 2; mt++)
        #pragma unroll
        for (int nt = 0; nt < 8; nt++) {
            int r  = m0 + wm * 32 + mt * 16 + g;
            int cc = n0 + wn * 64 + nt * 8 + 2 * t;
            float2 bb = *(const float2*)&bout[cc];
            *(float2*)&out[(size_t)r * DIMI + cc] =
                make_float2(acc[mt][nt][0] + bb.x, acc[mt][nt][1] + bb.y);
            *(float2*)&out[(size_t)(r + 8) * DIMI + cc] =
                make_float2(acc[mt][nt][2] + bb.x, acc[mt][nt][3] + bb.y);
        }
}

// ============================================================
// Launcher: round-10 fork-join stream overlap; splitx removed
// (fused into conv epilogue).
// ============================================================
extern "C" void kernel_launch(void* const* d_in, const int* in_sizes, int n_in,
                              void* d_out, int out_size) {
    (void)in_sizes; (void)n_in; (void)out_size;
    const float* in_f   = (const float*)d_in[0];
    const float* in_l   = (const float*)d_in[1];
    const float* rv     = (const float*)d_in[2];
    const float* cb     = (const float*)d_in[3];
    const float* W_in   = (const float*)d_in[4];
    const float* conv_w = (const float*)d_in[6];
    const float* W_out  = (const float*)d_in[8];
    const float* b_out  = (const float*)d_in[9];
    const int*   used   = (const int*)d_in[10];
    float* out = (float*)d_out;

    cudaFuncSetAttribute(k_vqtc,  cudaFuncAttributeMaxDynamicSharedMemorySize, VQ_SMEM);
    cudaFuncSetAttribute(k_gemm1, cudaFuncAttributeMaxDynamicSharedMemorySize, G1_SMEM);
    cudaFuncSetAttribute(k_conv,  cudaFuncAttributeMaxDynamicSharedMemorySize, CV_SMEM);
    cudaFuncSetAttribute(k_dec,   cudaFuncAttributeMaxDynamicSharedMemorySize, DEC_SMEM);

    cudaStream_t s1;
    cudaStreamCreateWithFlags(&s1, cudaStreamNonBlocking);
    cudaEvent_t eFork, ePrep, eRes, eJoin;
    cudaEventCreateWithFlags(&eFork, cudaEventDisableTiming);
    cudaEventCreateWithFlags(&ePrep, cudaEventDisableTiming);
    cudaEventCreateWithFlags(&eRes,  cudaEventDisableTiming);
    cudaEventCreateWithFlags(&eJoin, cudaEventDisableTiming);

    // fork: codebook + conv-weight prep on side stream, overlapped with gemm1
    cudaEventRecord(eFork, 0);
    cudaStreamWaitEvent(s1, eFork, 0);
    k_prep_c <<<576, 256, 0, s1>>>(conv_w);
    k_cbprep <<<2048, 256, 0, s1>>>(cb);
    cudaEventRecord(ePrep, s1);

    // main chain
    k_prep_wo<<<512, 256>>>(W_in, W_out);
    k_gemm1  <<<256, 256, G1_SMEM>>>(in_l, in_f);
    cudaStreamWaitEvent(0, ePrep, 0);       // conv needs g_wthi/g_wtlo + zeroed g_xnorm
    k_conv   <<<128, 256, CV_SMEM>>>();
    k_vqtc   <<<256, 256, VQ_SMEM>>>();
    k_respost<<<1024, 256>>>(cb, rv);

    // fork: final (scalars/tail of out) overlapped with decode GEMM
    cudaEventRecord(eRes, 0);
    cudaStreamWaitEvent(s1, eRes, 0);
    k_final  <<<1, 256, 0, s1>>>(used, out);
    k_dec    <<<256, 256, DEC_SMEM>>>(b_out, out);

    // join side stream back before returning (capture requirement)
    cudaEventRecord(eJoin, s1);
    cudaStreamWaitEvent(0, eJoin, 0);
}

// round 14
// speedup vs baseline: 8.8397x; 1.0183x over previous
#include <cuda_runtime.h>
#include <cuda_bf16.h>
#include <math.h>
#include <stdint.h>

// ---------------- problem dims ----------------
#define KB   16384
#define NN   8192
#define M1   32768
#define DD   128
#define DIMI 512
#define CAP  64

// ---------------- scratch ----------------
__device__ float g_h[M1 * DD];
__device__ float g_x[NN * DD];
__device__ float g_q[NN * DD];
__device__ float g_cnorm[KB];
__device__ float g_counts[KB];
__device__ int   g_idx[NN];
__device__ __nv_bfloat16 g_xs[NN * DD];           // x hi (bf16)
__device__ __nv_bfloat16 g_cs[(size_t)KB * DD];   // codebook hi (bf16)
__device__ float g_xnorm[NN];                     // |x|^2 (accumulated by conv)
__device__ int   g_cmax_bits;
__device__ int   g_ccount[NN];
__device__ int   g_cand[NN * CAP];
// tf32-split weights
__device__ float g_whi[DIMI * DD];                // W_in hi  [k][n]
__device__ float g_wlo[DIMI * DD];
__device__ float g_wthi[9 * DD * DD];             // conv w hi [kk][din][dout]
__device__ float g_wtlo[9 * DD * DD];
__device__ float g_ohi[DD * DIMI];                // W_out hi [k][n]
__device__ float g_olo[DD * DIMI];

// ---------------- helpers ----------------
__device__ __forceinline__ uint32_t smem_u32(const void* p) {
    uint32_t a;
    asm("{ .reg .u64 t; cvta.to.shared.u64 t, %1; cvt.u32.u64 %0, t; }" : "=r"(a) : "l"(p));
    return a;
}
__device__ __forceinline__ void cp16(uint32_t dst, const void* src) {
    asm volatile("cp.async.cg.shared.global [%0], [%1], 16;\n" :: "r"(dst), "l"(src));
}
__device__ __forceinline__ void cp16z(uint32_t dst, const void* src, int sz) {
    asm volatile("cp.async.cg.shared.global [%0], [%1], 16, %2;\n" :: "r"(dst), "l"(src), "r"(sz));
}
#define CP_COMMIT()  asm volatile("cp.async.commit_group;\n" ::: "memory")
#define CP_WAIT0()   asm volatile("cp.async.wait_group 0;\n" ::: "memory")
#define CP_WAIT1()   asm volatile("cp.async.wait_group 1;\n" ::: "memory")

__device__ __forceinline__ void ldsm4(uint32_t& r0, uint32_t& r1, uint32_t& r2, uint32_t& r3,
                                      uint32_t a) {
    asm volatile("ldmatrix.sync.aligned.m8n8.x4.shared.b16 {%0,%1,%2,%3}, [%4];"
                 : "=r"(r0), "=r"(r1), "=r"(r2), "=r"(r3) : "r"(a));
}
__device__ __forceinline__ void mma16816(float* d, const uint32_t* a, uint32_t b0, uint32_t b1) {
    asm volatile("mma.sync.aligned.m16n8k16.row.col.f32.bf16.bf16.f32 "
                 "{%0,%1,%2,%3}, {%4,%5,%6,%7}, {%8,%9}, {%0,%1,%2,%3};"
                 : "+f"(d[0]), "+f"(d[1]), "+f"(d[2]), "+f"(d[3])
                 : "r"(a[0]), "r"(a[1]), "r"(a[2]), "r"(a[3]), "r"(b0), "r"(b1));
}
__device__ __forceinline__ void mma_tf32(float* d, const uint32_t* a, uint32_t b0, uint32_t b1) {
    asm volatile("mma.sync.aligned.m16n8k8.row.col.f32.tf32.tf32.f32 "
                 "{%0,%1,%2,%3}, {%4,%5,%6,%7}, {%8,%9}, {%0,%1,%2,%3};"
                 : "+f"(d[0]), "+f"(d[1]), "+f"(d[2]), "+f"(d[3])
                 : "r"(a[0]), "r"(a[1]), "r"(a[2]), "r"(a[3]), "r"(b0), "r"(b1));
}
__device__ __forceinline__ void tf32split(float a, uint32_t& hi, uint32_t& lo) {
    asm("cvt.rna.tf32.f32 %0, %1;" : "=r"(hi) : "f"(a));
    float lof = a - __uint_as_float(hi);
    asm("cvt.rna.tf32.f32 %0, %1;" : "=r"(lo) : "f"(lof));
}
__device__ __forceinline__ uint32_t pack_bf16x2(float a, float b) {
    unsigned short s0 = __bfloat16_as_ushort(__float2bfloat16(a));
    unsigned short s1 = __bfloat16_as_ushort(__float2bfloat16(b));
    return (uint32_t)s0 | ((uint32_t)s1 << 16);
}

// ============================================================
// Prep kernels (unchanged)
// ============================================================
__global__ void k_prep_c(const float* __restrict__ cw) {
    int i = blockIdx.x * 256 + threadIdx.x;
    if (i == 0) g_cmax_bits = 0;
    if (i < 9 * DD * DD) {
        int dout = i & 127;
        int din  = (i >> 7) & 127;
        int kk   = i >> 14;
        float w = cw[(dout * DD + din) * 9 + kk];
        uint32_t hi, lo;
        tf32split(w, hi, lo);
        g_wthi[kk * (DD * DD) + din * DD + dout] = __uint_as_float(hi);
        g_wtlo[kk * (DD * DD) + din * DD + dout] = __uint_as_float(lo);
    }
}
__global__ void k_prep_wo(const float* __restrict__ W, const float* __restrict__ Wout) {
    int i = blockIdx.x * 256 + threadIdx.x;
    if (i < DIMI * DD) {
        uint32_t hi, lo;
        tf32split(W[i], hi, lo);
        g_whi[i] = __uint_as_float(hi);
        g_wlo[i] = __uint_as_float(lo);
    } else if (i < 2 * DIMI * DD) {
        int j = i - DIMI * DD;
        uint32_t hi, lo;
        tf32split(Wout[j], hi, lo);
        g_ohi[j] = __uint_as_float(hi);
        g_olo[j] = __uint_as_float(lo);
    }
}

__global__ void k_cbprep(const float* __restrict__ cb) {
    int k    = blockIdx.x * 8 + (threadIdx.x >> 5);
    int lane = threadIdx.x & 31;
    float4 v = ((const float4*)(cb + (size_t)k * DD))[lane];
    float s = v.x * v.x + v.y * v.y + v.z * v.z + v.w * v.w;
    uint2 u;
    u.x = pack_bf16x2(v.x, v.y);
    u.y = pack_bf16x2(v.z, v.w);
    ((uint2*)(g_cs + (size_t)k * DD))[lane] = u;
    #pragma unroll
    for (int o = 16; o; o >>= 1) s += __shfl_xor_sync(0xffffffffu, s, o);
    if (lane == 0) {
        g_cnorm[k]  = 0.5f * s;
        g_counts[k] = 0.f;
        if (k < NN) { g_ccount[k] = 0; g_xnorm[k] = 0.f; }
        atomicMax(&g_cmax_bits, __float_as_int(sqrtf(s)));
    }
}

// ============================================================
// GEMM1 via 3xTF32 (round-8 v1) — now takes m_base for half-split.
// ============================================================
#define G1_SMEM 143360
__global__ void __launch_bounds__(256, 1) k_gemm1(const float* __restrict__ A1,
                                                  const float* __restrict__ A0,
                                                  int m_base) {
    extern __shared__ char smc[];
    float*   fs = (float*)smc;
    uint32_t su = smem_u32(smc);
    int tid  = threadIdx.x;
    int wid  = tid >> 5;
    int lane = tid & 31;
    int g    = lane >> 2;
    int t    = lane & 3;
    int wm   = wid & 3;
    int wn   = wid >> 2;
    int m0   = m_base + blockIdx.x * 128;

    float acc[2][8][4];
    #pragma unroll
    for (int i = 0; i < 2; i++)
        #pragma unroll
        for (int j = 0; j < 8; j++)
            #pragma unroll
            for (int c = 0; c < 4; c++) acc[i][j][c] = 0.f;

    auto issue = [&](int ch, int buf) {
        int k0 = ch * 32;
        #pragma unroll
        for (int it = 0; it < 4; it++) {
            int idx = it * 256 + tid;
            int row = idx >> 3;
            int c4  = idx & 7;
            cp16(su + buf * 18432 + row * 144 + c4 * 16,
                 A1 + (size_t)(m0 + row) * DIMI + k0 + c4 * 4);
            cp16(su + 36864 + buf * 18432 + row * 144 + c4 * 16,
                 A0 + (size_t)(m0 + row) * DIMI + k0 + c4 * 4);
        }
        #pragma unroll
        for (int it = 0; it < 4; it++) {
            int idx = it * 256 + tid;
            int row = idx >> 5;
            int c   = idx & 31;
            cp16(su + 73728 + buf * 17408 + row * 544 + c * 16,
                 g_whi + (size_t)(k0 + row) * DD + c * 4);
            cp16(su + 108544 + buf * 17408 + row * 544 + c * 16,
                 g_wlo + (size_t)(k0 + row) * DD + c * 4);
        }
        CP_COMMIT();
    };

    issue(0, 0);
    issue(1, 1);

    for (int ch = 0; ch < 16; ch++) {
        int buf = ch & 1;
        if (ch < 15) { CP_WAIT1(); } else { CP_WAIT0(); }
        __syncthreads();

        const float* A1f = fs + buf * 4608;
        const float* A0f = fs + 9216 + buf * 4608;
        const float* BHf = fs + 18432 + buf * 4352;
        const float* BLf = fs + 27136 + buf * 4352;

        #pragma unroll
        for (int kc = 0; kc < 4; kc++) {
            uint32_t ah[2][4], al[2][4];
            #pragma unroll
            for (int mt = 0; mt < 2; mt++) {
                int r0 = wm * 32 + mt * 16 + g;
                int c0 = kc * 8 + t;
                float d0 = A1f[r0 * 36 + c0]           - A0f[r0 * 36 + c0];
                float d1 = A1f[(r0 + 8) * 36 + c0]     - A0f[(r0 + 8) * 36 + c0];
                float d2 = A1f[r0 * 36 + c0 + 4]       - A0f[r0 * 36 + c0 + 4];
                float d3 = A1f[(r0 + 8) * 36 + c0 + 4] - A0f[(r0 + 8) * 36 + c0 + 4];
                tf32split(d0, ah[mt][0], al[mt][0]);
                tf32split(d1, ah[mt][1], al[mt][1]);
                tf32split(d2, ah[mt][2], al[mt][2]);
                tf32split(d3, ah[mt][3], al[mt][3]);
            }
            uint32_t bh[8][2], bl[8][2];
            #pragma unroll
            for (int nt = 0; nt < 8; nt++) {
                int n  = wn * 64 + nt * 8 + g;
                int kr = kc * 8 + t;
                bh[nt][0] = __float_as_uint(BHf[kr * 136 + n]);
                bh[nt][1] = __float_as_uint(BHf[(kr + 4) * 136 + n]);
                bl[nt][0] = __float_as_uint(BLf[kr * 136 + n]);
                bl[nt][1] = __float_as_uint(BLf[(kr + 4) * 136 + n]);
            }
            #pragma unroll
            for (int mt = 0; mt < 2; mt++)
                #pragma unroll
                for (int nt = 0; nt < 8; nt++) {
                    mma_tf32(acc[mt][nt], ah[mt], bh[nt][0], bh[nt][1]);
                    mma_tf32(acc[mt][nt], al[mt], bh[nt][0], bh[nt][1]);
                    mma_tf32(acc[mt][nt], ah[mt], bl[nt][0], bl[nt][1]);
                }
        }
        __syncthreads();
        if (ch + 2 < 16) issue(ch + 2, buf);
    }

    #pragma unroll
    for (int mt = 0; mt < 2; mt++)
        #pragma unroll
        for (int nt = 0; nt < 8; nt++) {
            int r  = m0 + wm * 32 + mt * 16 + g;
            int cc = wn * 64 + nt * 8 + 2 * t;
            *(float2*)&g_h[(size_t)r * DD + cc]       = make_float2(acc[mt][nt][0], acc[mt][nt][1]);
            *(float2*)&g_h[(size_t)(r + 8) * DD + cc] = make_float2(acc[mt][nt][2], acc[mt][nt][3]);
        }
}

// ============================================================
// Conv via 3xTF32 + fused splitx epilogue — takes p_base for half-split.
// ============================================================
#define CV_SMEM 174080
__global__ void __launch_bounds__(256, 1) k_conv(int p_base) {
    extern __shared__ char smc[];
    float*   fs = (float*)smc;
    uint32_t su = smem_u32(smc);
    int tid  = threadIdx.x;
    int wid  = tid >> 5;
    int lane = tid & 31;
    int g    = lane >> 2;
    int t    = lane & 3;
    int wm   = wid & 1;
    int wn   = wid >> 1;
    int p0   = p_base + blockIdx.x * 64;

    float acc[2][4][4];
    #pragma unroll
    for (int i = 0; i < 2; i++)
        #pragma unroll
        for (int j = 0; j < 4; j++)
            #pragma unroll
            for (int c = 0; c < 4; c++) acc[i][j][c] = 0.f;

    auto issue = [&](int s, int buf) {
        int kk = s >> 1;
        int ch = s & 1;
        int kh = kk / 3, kw = kk % 3;
        #pragma unroll
        for (int it = 0; it < 4; it++) {
            int idx = it * 256 + tid;
            int pl  = idx >> 4;
            int cf  = idx & 15;
            int p  = p0 + pl;
            int b  = p >> 6;
            int jj = p & 63;
            int oh = jj >> 3, ow = jj & 7;
            int ih = 2 * oh - 1 + kh;
            int iw = 2 * ow - 1 + kw;
            bool valid = ((unsigned)ih < 16u) && ((unsigned)iw < 16u);
            const float* src = valid
                ? g_h + ((size_t)(b * 256 + ih * 16 + iw) * DD + ch * 64 + cf * 4)
                : g_h;
            cp16z(su + buf * 17408 + pl * 272 + cf * 16, src, valid ? 16 : 0);
        }
        #pragma unroll
        for (int it = 0; it < 8; it++) {
            int idx = it * 256 + tid;
            int row = idx >> 5;
            int c   = idx & 31;
            size_t so = (size_t)kk * (DD * DD) + (size_t)(ch * 64 + row) * DD + c * 4;
            cp16(su + 34816 + buf * 34816 + row * 544 + c * 16, g_wthi + so);
            cp16(su + 104448 + buf * 34816 + row * 544 + c * 16, g_wtlo + so);
        }
        CP_COMMIT();
    };

    issue(0, 0);
    issue(1, 1);

    for (int s = 0; s < 18; s++) {
        int buf = s & 1;
        if (s < 17) { CP_WAIT1(); } else { CP_WAIT0(); }
        __syncthreads();

        const float* Af  = fs + buf * 4352;
        const float* BHf = fs + 8704 + buf * 8704;
        const float* BLf = fs + 26112 + buf * 8704;

        #pragma unroll
        for (int kc = 0; kc < 8; kc++) {
            uint32_t ah[2][4], al[2][4];
            #pragma unroll
            for (int mt = 0; mt < 2; mt++) {
                int r0 = wm * 32 + mt * 16 + g;
                int c0 = kc * 8 + t;
                tf32split(Af[r0 * 68 + c0],           ah[mt][0], al[mt][0]);
                tf32split(Af[(r0 + 8) * 68 + c0],     ah[mt][1], al[mt][1]);
                tf32split(Af[r0 * 68 + c0 + 4],       ah[mt][2], al[mt][2]);
                tf32split(Af[(r0 + 8) * 68 + c0 + 4], ah[mt][3], al[mt][3]);
            }
            uint32_t bh[4][2], bl[4][2];
            #pragma unroll
            for (int nt = 0; nt < 4; nt++) {
                int n  = wn * 32 + nt * 8 + g;
                int kr = kc * 8 + t;
                bh[nt][0] = __float_as_uint(BHf[kr * 136 + n]);
                bh[nt][1] = __float_as_uint(BHf[(kr + 4) * 136 + n]);
                bl[nt][0] = __float_as_uint(BLf[kr * 136 + n]);
                bl[nt][1] = __float_as_uint(BLf[(kr + 4) * 136 + n]);
            }
            #pragma unroll
            for (int mt = 0; mt < 2; mt++)
                #pragma unroll
                for (int nt = 0; nt < 4; nt++) {
                    mma_tf32(acc[mt][nt], ah[mt], bh[nt][0], bh[nt][1]);
                    mma_tf32(acc[mt][nt], al[mt], bh[nt][0], bh[nt][1]);
                    mma_tf32(acc[mt][nt], ah[mt], bl[nt][0], bl[nt][1]);
                }
        }
        __syncthreads();
        if (s + 2 < 18) issue(s + 2, buf);
    }

    // fused epilogue: g_x (fp32) + g_xs (bf16) + |x|^2 accumulation
    float sq0[2] = {0.f, 0.f};
    float sq1[2] = {0.f, 0.f};
    #pragma unroll
    for (int mt = 0; mt < 2; mt++) {
        #pragma unroll
        for (int nt = 0; nt < 4; nt++) {
            int r  = p0 + wm * 32 + mt * 16 + g;
            int cc = wn * 32 + nt * 8 + 2 * t;
            float a0 = acc[mt][nt][0], a1 = acc[mt][nt][1];
            float a2 = acc[mt][nt][2], a3 = acc[mt][nt][3];
            *(float2*)&g_x[(size_t)r * DD + cc]       = make_float2(a0, a1);
            *(float2*)&g_x[(size_t)(r + 8) * DD + cc] = make_float2(a2, a3);
            *(uint32_t*)&g_xs[(size_t)r * DD + cc]       = pack_bf16x2(a0, a1);
            *(uint32_t*)&g_xs[(size_t)(r + 8) * DD + cc] = pack_bf16x2(a2, a3);
            sq0[mt] += a0 * a0 + a1 * a1;
            sq1[mt] += a2 * a2 + a3 * a3;
        }
    }
    #pragma unroll
    for (int mt = 0; mt < 2; mt++) {
        sq0[mt] += __shfl_xor_sync(0xffffffffu, sq0[mt], 1);
        sq0[mt] += __shfl_xor_sync(0xffffffffu, sq0[mt], 2);
        sq1[mt] += __shfl_xor_sync(0xffffffffu, sq1[mt], 1);
        sq1[mt] += __shfl_xor_sync(0xffffffffu, sq1[mt], 2);
        if (t == 0) {
            int r = p0 + wm * 32 + mt * 16 + g;
            atomicAdd(&g_xnorm[r], sq0[mt]);
            atomicAdd(&g_xnorm[r + 8], sq1[mt]);
        }
    }
}

// ============================================================
// VQ approximate pass (round-8 v2, measured-best) — takes tt_base.
// ============================================================
#define LDB      272
#define A_OFF    0
#define B_OFF    34816
#define CNS_OFF  104448
#define EB2_OFF  105472
#define RMIN_OFF 105984
#define RM_OFF   108032
#define VQ_SMEM  108544
#define NIT 32

__device__ __forceinline__ void vq_loadB(uint32_t su, int buf, int kglob, int tid) {
    #pragma unroll
    for (int t = 0; t < 8; t++) {
        int j   = t * 256 + tid;
        int row = j >> 4;
        int c   = j & 15;
        cp16(su + B_OFF + buf * 34816 + row * LDB + c * 16,
             (const char*)g_cs + ((size_t)(kglob + row) * DD + c * 8) * 2);
    }
}

__global__ void __launch_bounds__(256, 2) k_vqtc(int tt_base) {
    extern __shared__ char smc[];
    uint32_t su = smem_u32(smc);
    int tid  = threadIdx.x;
    int wid  = tid >> 5;
    int lane = tid & 31;
    int wm   = wid & 1;
    int wn   = wid >> 1;
    int tt   = tt_base + (blockIdx.x >> 2);
    int sp   = blockIdx.x & 3;
    int kb0  = sp * 4096;

    float* cns  = (float*)(smc + CNS_OFF);
    float* eb2  = (float*)(smc + EB2_OFF);
    float* rmin = (float*)(smc + RMIN_OFF);
    float* rm   = (float*)(smc + RM_OFF);

    #pragma unroll
    for (int t = 0; t < 8; t++) {
        int i   = t * 256 + tid;
        int row = i >> 4;
        int c   = i & 15;
        cp16(su + A_OFF + row * LDB + c * 16,
             (const char*)g_xs + ((size_t)(tt * 128 + row) * DD + c * 8) * 2);
    }
    vq_loadB(su, 0, kb0, tid);
    CP_COMMIT();
    vq_loadB(su, 1, kb0 + 128, tid);
    CP_COMMIT();

    if (tid < 128) {
        cns[tid]       = g_cnorm[kb0 + tid];
        cns[128 + tid] = g_cnorm[kb0 + 128 + tid];
        float cmax = __int_as_float(g_cmax_bits);
        float xn = sqrtf(g_xnorm[tt * 128 + tid]);
        eb2[tid] = 2.f * (0.0041f * xn * cmax) + 0.1f;
        rm[tid]  = 1e30f;
    }
    CP_WAIT1();
    __syncthreads();

    uint32_t aBase = su + A_OFF + (wm * 64 + (lane & 15)) * LDB + (lane >> 4) * 16;
    uint32_t bBase = su + B_OFF + (wn * 32 + (lane & 15)) * LDB + (lane >> 4) * 16;

    for (int it = 0; it < NIT; it++) {
        int buf = it & 1;
        float acc[4][4][4];
        #pragma unroll
        for (int mt = 0; mt < 4; mt++)
            #pragma unroll
            for (int nt = 0; nt < 4; nt++)
                #pragma unroll
                for (int c = 0; c < 4; c++) acc[mt][nt][c] = 0.f;

        #pragma unroll
        for (int ks = 0; ks < 8; ks++) {
            uint32_t a[4][4];
            #pragma unroll
            for (int mt = 0; mt < 4; mt++)
                ldsm4(a[mt][0], a[mt][1], a[mt][2], a[mt][3],
                      aBase + mt * (16 * LDB) + ks * 32);
            uint32_t b0[4], b1[4];
            #pragma unroll
            for (int np = 0; np < 2; np++) {
                uint32_t r0, r1, r2, r3;
                ldsm4(r0, r1, r2, r3,
                      bBase + buf * 34816 + np * (16 * LDB) + ks * 32);
                b0[np * 2] = r0; b1[np * 2] = r2;
                b0[np * 2 + 1] = r1; b1[np * 2 + 1] = r3;
            }
            #pragma unroll
            for (int mt = 0; mt < 4; mt++)
                #pragma unroll
                for (int nt = 0; nt < 4; nt++)
                    mma16816(acc[mt][nt], a[mt], b0[nt], b1[nt]);
        }

        float lm[8];
        #pragma unroll
        for (int mt = 0; mt < 4; mt++) {
            #pragma unroll
            for (int h = 0; h < 2; h++) {
                float m = 1e30f;
                #pragma unroll
                for (int nt = 0; nt < 4; nt++) {
                    int colb = wn * 32 + nt * 8 + (lane & 3) * 2;
                    float s0 = cns[buf * 128 + colb]     - acc[mt][nt][h * 2];
                    float s1 = cns[buf * 128 + colb + 1] - acc[mt][nt][h * 2 + 1];
                    m = fminf(m, fminf(s0, s1));
                }
                lm[mt * 2 + h] = m;
            }
        }
        #pragma unroll
        for (int s = 0; s < 8; s++) {
            lm[s] = fminf(lm[s], __shfl_xor_sync(0xffffffffu, lm[s], 1));
            lm[s] = fminf(lm[s], __shfl_xor_sync(0xffffffffu, lm[s], 2));
        }
        if ((lane & 3) == 0) {
            #pragma unroll
            for (int mt = 0; mt < 4; mt++)
                #pragma unroll
                for (int h = 0; h < 2; h++) {
                    int row = wm * 64 + mt * 16 + (lane >> 2) + h * 8;
                    rmin[wn * 128 + row] = lm[mt * 2 + h];
                }
        }
        __syncthreads();
        if (tid < 128) {
            float tm = fminf(fminf(rmin[tid], rmin[128 + tid]),
                             fminf(rmin[256 + tid], rmin[384 + tid]));
            float r  = fminf(rm[tid], tm);
            rm[tid]  = r;
            rmin[tid] = r + eb2[tid];
        }
        __syncthreads();

        #pragma unroll
        for (int mt = 0; mt < 4; mt++) {
            #pragma unroll
            for (int h = 0; h < 2; h++) {
                int row = wm * 64 + mt * 16 + (lane >> 2) + h * 8;
                float thrv = rmin[row];
                if (lm[mt * 2 + h] < thrv) {
                    int tok = tt * 128 + row;
                    #pragma unroll
                    for (int nt = 0; nt < 4; nt++) {
                        int colb = wn * 32 + nt * 8 + (lane & 3) * 2;
                        #pragma unroll
                        for (int cc = 0; cc < 2; cc++) {
                            float sc = cns[buf * 128 + colb + cc] - acc[mt][nt][h * 2 + cc];
                            if (sc < thrv) {
                                int pos = atomicAdd(&g_ccount[tok], 1);
                                if (pos < CAP)
                                    g_cand[tok * CAP + pos] = kb0 + it * 128 + colb + cc;
                            }
                        }
                    }
                }
            }
        }
        __syncthreads();

        if (it + 2 < NIT) {
            vq_loadB(su, buf, kb0 + (it + 2) * 128, tid);
            CP_COMMIT();
            if (tid < 128) cns[buf * 128 + tid] = g_cnorm[kb0 + (it + 2) * 128 + tid];
        }
        if (it + 1 < NIT) {
            if (it + 2 < NIT) { CP_WAIT1(); } else { CP_WAIT0(); }
            __syncthreads();
        }
    }
}

// ============================================================
// Fused exact fp32 re-rank + NSVQ post (unchanged)
// ============================================================
__global__ void k_respost(const float* __restrict__ cb, const float* __restrict__ rv) {
    int gw   = (blockIdx.x * blockDim.x + threadIdx.x) >> 5;
    int lane = threadIdx.x & 31;
    if (gw >= NN) return;
    int cnt = g_ccount[gw];
    const float* xp = g_x + (size_t)gw * DD;
    float x4[4];
    #pragma unroll
    for (int t = 0; t < 4; t++) x4[t] = xp[lane + t * 32];

    float bestv = 1e30f;
    int   bestk = KB;

    if (cnt <= CAP) {
        for (int i = 0; i < cnt; i++) {
            int k = g_cand[gw * CAP + i];
            const float* cp = cb + (size_t)k * DD;
            float p = 0.f;
            #pragma unroll
            for (int t = 0; t < 4; t++) p = fmaf(x4[t], cp[lane + t * 32], p);
            #pragma unroll
            for (int o = 16; o; o >>= 1) p += __shfl_xor_sync(0xffffffffu, p, o);
            float sc = g_cnorm[k] - p;
            if (sc < bestv || (sc == bestv && k < bestk)) { bestv = sc; bestk = k; }
        }
    } else {
        for (int k = lane; k < KB; k += 32) {
            const float* cp = cb + (size_t)k * DD;
            float p = 0.f;
            for (int d = 0; d < DD; d++) p = fmaf(__ldg(xp + d), __ldg(cp + d), p);
            float sc = g_cnorm[k] - p;
            if (sc < bestv || (sc == bestv && k < bestk)) { bestv = sc; bestk = k; }
        }
        #pragma unroll
        for (int o = 16; o; o >>= 1) {
            float ov = __shfl_down_sync(0xffffffffu, bestv, o);
            int   ok = __shfl_down_sync(0xffffffffu, bestk, o);
            if (ov < bestv || (ov == bestv && ok < bestk)) { bestv = ov; bestk = ok; }
        }
        bestk = __shfl_sync(0xffffffffu, bestk, 0);
    }

    const float* cp = cb + (size_t)bestk * DD;
    const float* rp = rv + (size_t)gw * DD;
    float rr[4];
    float sr = 0.f, sn = 0.f;
    #pragma unroll
    for (int t = 0; t < 4; t++) {
        int d = lane + t * 32;
        float cv = cp[d], rvv = rp[d];
        rr[t] = rvv;
        float df = x4[t] - cv;
        sr += df * df;
        sn += rvv * rvv;
    }
    #pragma unroll
    for (int o = 16; o; o >>= 1) {
        sr += __shfl_xor_sync(0xffffffffu, sr, o);
        sn += __shfl_xor_sync(0xffffffffu, sn, o);
    }
    float ratio = sqrtf(sr) / sqrtf(sn) + 1e-12f;
    float* qp = g_q + (size_t)gw * DD;
    #pragma unroll
    for (int t = 0; t < 4; t++) qp[lane + t * 32] = x4[t] + ratio * rr[t];
    if (lane == 0) {
        g_idx[gw] = bestk;
        atomicAdd(&g_counts[bestk], 1.0f);
    }
}

// ============================================================
// Final scalars (unchanged)
// ============================================================
__global__ void k_final(const int* __restrict__ used, float* __restrict__ out) {
    __shared__ float red[256];
    int tid = threadIdx.x;
    float s = 0.f;
    for (int k = tid; k < KB; k += 256) {
        float p = g_counts[k] * (1.0f / 8192.0f);
        s += p * logf(p + 1e-12f);
    }
    red[tid] = s;
    __syncthreads();
    for (int o = 128; o; o >>= 1) {
        if (tid < o) red[tid] += red[tid + o];
        __syncthreads();
    }
    if (tid == 0) out[4194304] = expf(-red[0]);
    for (int k = tid; k < KB; k += 256)
        out[4194305 + k] = (float)(used[k] + (int)g_counts[k]);
    for (int n = tid; n < NN; n += 256)
        out[4194305 + KB + n] = (float)g_idx[n];
}

// ============================================================
// Decode GEMM via 3xTF32 (unchanged)
// ============================================================
#define DEC_SMEM 104448
__global__ void __launch_bounds__(256, 1) k_dec(const float* __restrict__ bout,
                                                float* __restrict__ out) {
    extern __shared__ char smc[];
    float*   fs = (float*)smc;
    uint32_t su = smem_u32(smc);
    int tid  = threadIdx.x;
    int wid  = tid >> 5;
    int lane = tid & 31;
    int g    = lane >> 2;
    int t    = lane & 3;
    int wm   = wid & 3;
    int wn   = wid >> 2;
    int m0   = (blockIdx.x >> 2) * 128;
    int n0   = (blockIdx.x & 3) * 128;
    int bg0  = m0 >> 6;

    float acc[2][8][4];
    #pragma unroll
    for (int i = 0; i < 2; i++)
        #pragma unroll
        for (int j = 0; j < 8; j++)
            #pragma unroll
            for (int c = 0; c < 4; c++) acc[i][j][c] = 0.f;

    auto issue = [&](int ch, int buf) {
        int k0 = ch * 32;
        #pragma unroll
        for (int it = 0; it < 4; it++) {
            int idx = it * 256 + tid;
            int d   = idx >> 5;
            int r   = idx & 31;
            int bgl = r >> 4;
            int j4  = r & 15;
            cp16(su + buf * 17408 + d * 544 + bgl * 256 + j4 * 16,
                 g_q + (size_t)(bg0 + bgl) * 8192 + (size_t)(k0 + d) * 64 + j4 * 4);
        }
        #pragma unroll
        for (int it = 0; it < 4; it++) {
            int idx = it * 256 + tid;
            int row = idx >> 5;
            int c   = idx & 31;
            cp16(su + 34816 + buf * 17408 + row * 544 + c * 16,
                 g_ohi + (size_t)(k0 + row) * DIMI + n0 + c * 4);
            cp16(su + 69632 + buf * 17408 + row * 544 + c * 16,
                 g_olo + (size_t)(k0 + row) * DIMI + n0 + c * 4);
        }
        CP_COMMIT();
    };

    issue(0, 0);
    issue(1, 1);

    for (int ch = 0; ch < 4; ch++) {
        int buf = ch & 1;
        if (ch < 3) { CP_WAIT1(); } else { CP_WAIT0(); }
        __syncthreads();

        const float* Af  = fs + buf * 4352;
        const float* BHf = fs + 8704 + buf * 4352;
        const float* BLf = fs + 17408 + buf * 4352;

        #pragma unroll
        for (int kc = 0; kc < 4; kc++) {
            uint32_t ah[2][4], al[2][4];
            #pragma unroll
            for (int mt = 0; mt < 2; mt++) {
                int r0 = wm * 32 + mt * 16 + g;
                int c0 = kc * 8 + t;
                float d0 = Af[c0 * 136 + r0];
                float d1 = Af[c0 * 136 + r0 + 8];
                float d2 = Af[(c0 + 4) * 136 + r0];
                float d3 = Af[(c0 + 4) * 136 + r0 + 8];
                tf32split(d0, ah[mt][0], al[mt][0]);
                tf32split(d1, ah[mt][1], al[mt][1]);
                tf32split(d2, ah[mt][2], al[mt][2]);
                tf32split(d3, ah[mt][3], al[mt][3]);
            }
            uint32_t bh[8][2], bl[8][2];
            #pragma unroll
            for (int nt = 0; nt < 8; nt++) {
                int n  = wn * 64 + nt * 8 + g;
                int kr = kc * 8 + t;
                bh[nt][0] = __float_as_uint(BHf[kr * 136 + n]);
                bh[nt][1] = __float_as_uint(BHf[(kr + 4) * 136 + n]);
                bl[nt][0] = __float_as_uint(BLf[kr * 136 + n]);
                bl[nt][1] = __float_as_uint(BLf[(kr + 4) * 136 + n]);
            }
            #pragma unroll
            for (int mt = 0; mt < 2; mt++)
                #pragma unroll
                for (int nt = 0; nt < 8; nt++) {
                    mma_tf32(acc[mt][nt], ah[mt], bh[nt][0], bh[nt][1]);
                    mma_tf32(acc[mt][nt], al[mt], bh[nt][0], bh[nt][1]);
                    mma_tf32(acc[mt][nt], ah[mt], bl[nt][0], bl[nt][1]);
                }
        }
        __syncthreads();
        if (ch + 2 < 4) issue(ch + 2, buf);
    }

    #pragma unroll
    for (int mt = 0; mt < 2; mt++)
        #pragma unroll
        for (int nt = 0; nt < 8; nt++) {
            int r  = m0 + wm * 32 + mt * 16 + g;
            int cc = n0 + wn * 64 + nt * 8 + 2 * t;
            float2 bb = *(const float2*)&bout[cc];
            *(float2*)&out[(size_t)r * DIMI + cc] =
                make_float2(acc[mt][nt][0] + bb.x, acc[mt][nt][1] + bb.y);
            *(float2*)&out[(size_t)(r + 8) * DIMI + cc] =
                make_float2(acc[mt][nt][2] + bb.x, acc[mt][nt][3] + bb.y);
        }
}

// ============================================================
// Launcher: two half-chains pipelined across streams.
//   s0: prep_wo, gemm1_a [evG1A], gemm1_b, [wait ePrep] conv_b, vqtc_b,
//       [wait evVQA] respost, [fork final] dec
//   s1: prep_c, cbprep [ePrep], [wait evG1A] conv_a, vqtc_a [evVQA]
// ============================================================
extern "C" void kernel_launch(void* const* d_in, const int* in_sizes, int n_in,
                              void* d_out, int out_size) {
    (void)in_sizes; (void)n_in; (void)out_size;
    const float* in_f   = (const float*)d_in[0];
    const float* in_l   = (const float*)d_in[1];
    const float* rv     = (const float*)d_in[2];
    const float* cb     = (const float*)d_in[3];
    const float* W_in   = (const float*)d_in[4];
    const float* conv_w = (const float*)d_in[6];
    const float* W_out  = (const float*)d_in[8];
    const float* b_out  = (const float*)d_in[9];
    const int*   used   = (const int*)d_in[10];
    float* out = (float*)d_out;

    cudaFuncSetAttribute(k_vqtc,  cudaFuncAttributeMaxDynamicSharedMemorySize, VQ_SMEM);
    cudaFuncSetAttribute(k_gemm1, cudaFuncAttributeMaxDynamicSharedMemorySize, G1_SMEM);
    cudaFuncSetAttribute(k_conv,  cudaFuncAttributeMaxDynamicSharedMemorySize, CV_SMEM);
    cudaFuncSetAttribute(k_dec,   cudaFuncAttributeMaxDynamicSharedMemorySize, DEC_SMEM);

    cudaStream_t s1;
    cudaStreamCreateWithFlags(&s1, cudaStreamNonBlocking);
    cudaEvent_t eFork, ePrep, eG1A, eVQA, eRes, eJoin;
    cudaEventCreateWithFlags(&eFork, cudaEventDisableTiming);
    cudaEventCreateWithFlags(&ePrep, cudaEventDisableTiming);
    cudaEventCreateWithFlags(&eG1A,  cudaEventDisableTiming);
    cudaEventCreateWithFlags(&eVQA,  cudaEventDisableTiming);
    cudaEventCreateWithFlags(&eRes,  cudaEventDisableTiming);
    cudaEventCreateWithFlags(&eJoin, cudaEventDisableTiming);

    // fork side stream
    cudaEventRecord(eFork, 0);
    cudaStreamWaitEvent(s1, eFork, 0);
    k_prep_c <<<576, 256, 0, s1>>>(conv_w);
    k_cbprep <<<2048, 256, 0, s1>>>(cb);
    cudaEventRecord(ePrep, s1);

    // main chain: weights prep + first gemm1 half
    k_prep_wo<<<512, 256>>>(W_in, W_out);
    k_gemm1  <<<128, 256, G1_SMEM>>>(in_l, in_f, 0);
    cudaEventRecord(eG1A, 0);
    k_gemm1  <<<128, 256, G1_SMEM>>>(in_l, in_f, 16384);

    // side chain: conv_a + vqtc_a (tokens 0..4095) overlap gemm1_b/conv_b
    cudaStreamWaitEvent(s1, eG1A, 0);
    k_conv   <<<64, 256, CV_SMEM, s1>>>(0);
    k_vqtc   <<<128, 256, VQ_SMEM, s1>>>(0);
    cudaEventRecord(eVQA, s1);

    // main chain: conv_b + vqtc_b (tokens 4096..8191)
    cudaStreamWaitEvent(0, ePrep, 0);       // conv needs weights + zeroed g_xnorm
    k_conv   <<<64, 256, CV_SMEM>>>(4096);
    k_vqtc   <<<128, 256, VQ_SMEM>>>(32);
    cudaStreamWaitEvent(0, eVQA, 0);        // join: both halves done
    k_respost<<<1024, 256>>>(cb, rv);

    // fork: final overlapped with decode GEMM
    cudaEventRecord(eRes, 0);
    cudaStreamWaitEvent(s1, eRes, 0);
    k_final  <<<1, 256, 0, s1>>>(used, out);
    k_dec    <<<256, 256, DEC_SMEM>>>(b_out, out);

    // join side stream back before returning
    cudaEventRecord(eJoin, s1);
    cudaStreamWaitEvent(0, eJoin, 0);
}